// round 1
// baseline (speedup 1.0000x reference)
#include <cuda_runtime.h>
#include <math.h>

#define Bn   2
#define Tn   2048
#define Cn   1024
#define Hn   16
#define HDn  64
#define BTn  (Bn*Tn)          // 4096
#define QMAXF 127.0f

// ---------------- scratch (module globals; no allocation) ----------------
__device__ float g_hq [BTn*Cn];        // 16 MB  LN fake-quant output
__device__ float g_w1q[3*Cn*Cn];       // 12 MB
__device__ float g_w2q[Cn*Cn];         //  4 MB
__device__ float g_qkv[BTn*3*Cn];      // 48 MB
__device__ float g_y  [BTn*Cn];        // 16 MB  attention out, then fake-quant in place
__device__ float g_proj[BTn*Cn];       // 16 MB

__device__ __forceinline__ float warp_max(float v){
#pragma unroll
    for (int o=16;o;o>>=1) v = fmaxf(v, __shfl_xor_sync(0xffffffffu, v, o));
    return v;
}
__device__ __forceinline__ float warp_sum(float v){
#pragma unroll
    for (int o=16;o;o>>=1) v += __shfl_xor_sync(0xffffffffu, v, o);
    return v;
}

// ---------------- kernel 1: int8 LN + group-32 fake-quant ----------------
__global__ void ln_quant_kernel(const int* __restrict__ qx, const float* __restrict__ sx,
                                const float* __restrict__ meanp, const float* __restrict__ rstdp,
                                const float* __restrict__ lnw){
    int r = blockIdx.x, c = threadIdx.x;              // block = one (b,t) row, 1024 thr
    float xv = (float)qx[r*Cn + c] * sx[r*(Cn/32) + (c>>5)];
    float h  = (xv - meanp[r]) * rstdp[r] * lnw[c];
    float gm = warp_max(fabsf(h));                    // group of 32 == warp
    float s  = fmaxf(gm / QMAXF, 1e-8f);
    float q  = rintf(h / s);                          // nearest-even == jnp.round
    q = fminf(fmaxf(q, -QMAXF), QMAXF);
    g_hq[r*Cn + c] = q * s;
}

// ---------------- kernel 2: row-wise group-32 fake-quant ----------------
// isel: 0 = external input pointer, 1 = g_y.  osel: 0 = g_w1q, 1 = g_w2q, 2 = g_y
__global__ void rowquant_kernel(const float* __restrict__ in_ext, int isel, int osel){
    const float* in = (isel == 1) ? g_y : in_ext;
    float* out = (osel == 0) ? g_w1q : (osel == 1) ? g_w2q : g_y;
    int r = blockIdx.x, c = threadIdx.x;
    float h  = in[r*Cn + c];
    float gm = warp_max(fabsf(h));
    float s  = fmaxf(gm / QMAXF, 1e-8f);
    float q  = rintf(h / s);
    q = fminf(fmaxf(q, -QMAXF), QMAXF);
    out[r*Cn + c] = q * s;
}

// ---------------- kernel 3: fp32 GEMM  C[M,N] = A[M,K] * B[N,K]^T ----------------
// Tile 64(M) x 128(N) x 16(K), 256 threads, 4x8 per-thread microtile.
__global__ __launch_bounds__(256) void gemm_kernel(int which){
    const float* A; const float* Bm; float* Cm; int N;
    if (which == 0){ A = g_hq; Bm = g_w1q; Cm = g_qkv; N = 3*Cn; }
    else           { A = g_y;  Bm = g_w2q; Cm = g_proj; N = Cn;  }
    const int K = Cn;

    __shared__ __align__(16) float As[16][68];    // [k][m] (padded)
    __shared__ __align__(16) float Bs[16][132];   // [k][n] (padded)

    int tid = threadIdx.x;
    int tx = tid & 15, ty = tid >> 4;
    int bm = blockIdx.y << 6, bn = blockIdx.x << 7;
    int am  = tid >> 2, ak = (tid & 3) << 2;      // A loader: 1 float4 each
    int bnr = tid >> 1, bk = (tid & 1) << 3;      // B loader: 2 float4 each

    float acc[4][8];
#pragma unroll
    for (int i=0;i<4;i++)
#pragma unroll
        for (int j=0;j<8;j++) acc[i][j] = 0.f;

    for (int k0 = 0; k0 < K; k0 += 16){
        float4 av  = *(const float4*)(A  + (bm+am )*K + k0 + ak);
        float4 bv0 = *(const float4*)(Bm + (bn+bnr)*K + k0 + bk);
        float4 bv1 = *(const float4*)(Bm + (bn+bnr)*K + k0 + bk + 4);
        __syncthreads();
        As[ak+0][am] = av.x;  As[ak+1][am] = av.y;  As[ak+2][am] = av.z;  As[ak+3][am] = av.w;
        Bs[bk+0][bnr]= bv0.x; Bs[bk+1][bnr]= bv0.y; Bs[bk+2][bnr]= bv0.z; Bs[bk+3][bnr]= bv0.w;
        Bs[bk+4][bnr]= bv1.x; Bs[bk+5][bnr]= bv1.y; Bs[bk+6][bnr]= bv1.z; Bs[bk+7][bnr]= bv1.w;
        __syncthreads();
#pragma unroll
        for (int kk=0; kk<16; kk++){
            float4 a4 = *(const float4*)&As[kk][ty<<2];
            float4 b0 = *(const float4*)&Bs[kk][tx<<2];
            float4 b1 = *(const float4*)&Bs[kk][64 + (tx<<2)];
            float aa[4] = {a4.x,a4.y,a4.z,a4.w};
            float bb[8] = {b0.x,b0.y,b0.z,b0.w,b1.x,b1.y,b1.z,b1.w};
#pragma unroll
            for (int i=0;i<4;i++)
#pragma unroll
                for (int j=0;j<8;j++) acc[i][j] += aa[i]*bb[j];
        }
    }
#pragma unroll
    for (int i=0;i<4;i++){
        int mrow = bm + (ty<<2) + i;
        float4 c0 = make_float4(acc[i][0],acc[i][1],acc[i][2],acc[i][3]);
        float4 c1 = make_float4(acc[i][4],acc[i][5],acc[i][6],acc[i][7]);
        *(float4*)(Cm + mrow*N + bn +      (tx<<2)) = c0;
        *(float4*)(Cm + mrow*N + bn + 64 + (tx<<2)) = c1;
    }
}

// ---------------- kernel 4: causal flash attention (fp32) ----------------
// block = (q-tile 64, head, batch); 256 thr; warp w owns query rows w*8..w*8+7.
__global__ __launch_bounds__(256) void attn_kernel(){
    __shared__ __align__(16) float Qs[64*64];     // [q][d], pre-scaled by 1/8
    __shared__ __align__(16) float Ks[32*68];     // [k][d] padded
    __shared__ __align__(16) float Vs[32*64];     // [k][d]

    int qt = blockIdx.x, h = blockIdx.y, b = blockIdx.z;
    int tid = threadIdx.x, w = tid >> 5, l = tid & 31;
    int qs = qt << 6;
    const float* base = g_qkv + (b*Tn)*3*Cn + h*HDn;

#pragma unroll
    for (int it=0; it<4; it++){                    // load Q tile, scale by 1/sqrt(hd)
        int idx = tid + it*256;
        int r = idx >> 4, d4 = (idx & 15) << 2;
        float4 v = *(const float4*)(base + (qs+r)*3*Cn + d4);
        v.x *= 0.125f; v.y *= 0.125f; v.z *= 0.125f; v.w *= 0.125f;
        *(float4*)&Qs[r*64 + d4] = v;
    }

    float m[8], lsum[8], ax[8], ay[8];
#pragma unroll
    for (int r=0;r<8;r++){ m[r] = -INFINITY; lsum[r]=0.f; ax[r]=0.f; ay[r]=0.f; }

    int ntiles = (qs + 64) >> 5;                   // causal: k < qs+64
    for (int kt=0; kt<ntiles; kt++){
        int ks = kt << 5;
        __syncthreads();
#pragma unroll
        for (int it=0; it<2; it++){                // load K,V tiles (32 x 64)
            int idx = tid + it*256;
            int kr = idx >> 4, d4 = (idx & 15) << 2;
            const float* rowp = base + (ks+kr)*3*Cn;
            float4 kv = *(const float4*)(rowp +   Cn + d4);
            float4 vv = *(const float4*)(rowp + 2*Cn + d4);
            *(float4*)&Ks[kr*68 + d4] = kv;
            *(float4*)&Vs[kr*64 + d4] = vv;
        }
        __syncthreads();

        int kg = ks + l;
        const float4* K4 = (const float4*)(Ks + l*68);
        const float2* V2 = (const float2*)Vs;
#pragma unroll
        for (int r=0;r<8;r++){
            int rg = (w<<3) + r;
            const float4* Q4 = (const float4*)(Qs + rg*64);
            float s = 0.f;
#pragma unroll
            for (int d4=0; d4<16; d4++){
                float4 a = Q4[d4], bq = K4[d4];
                s += a.x*bq.x; s += a.y*bq.y; s += a.z*bq.z; s += a.w*bq.w;
            }
            if (kg > qs + rg) s = -1e30f;          // causal mask (matches reference)
            float mn = fmaxf(m[r], warp_max(s));
            float alpha = __expf(m[r] - mn);
            float p = __expf(s - mn);
            lsum[r] = lsum[r]*alpha + warp_sum(p);
            m[r] = mn;
            float a0 = ax[r]*alpha, a1 = ay[r]*alpha;
#pragma unroll
            for (int kk=0; kk<32; kk++){
                float pk = __shfl_sync(0xffffffffu, p, kk);
                float2 vv = V2[(kk<<5) + l];
                a0 += pk*vv.x; a1 += pk*vv.y;
            }
            ax[r] = a0; ay[r] = a1;
        }
    }
#pragma unroll
    for (int r=0;r<8;r++){
        int rg = (w<<3) + r;
        float inv = 1.0f / lsum[r];
        float2 o; o.x = ax[r]*inv; o.y = ay[r]*inv;
        *(float2*)&g_y[(b*Tn + qs + rg)*Cn + h*HDn + (l<<1)] = o;
    }
}

// ---------------- kernel 5: residual + stats + output quant + pack ----------------
__global__ void final_kernel(const float* __restrict__ x, float* __restrict__ out, long long osz){
    __shared__ float red[33];
    int r = blockIdx.x, c = threadIdx.x;
    float v = x[r*Cn + c] + g_proj[r*Cn + c];

    float s1 = warp_sum(v);
    if ((c & 31) == 0) red[c>>5] = s1;
    __syncthreads();
    if (c < 32){
        float t = warp_sum(red[c]);
        if (c == 0) red[32] = t * (1.0f/Cn);
    }
    __syncthreads();
    float mu = red[32];
    float dd = v - mu;
    float s2 = warp_sum(dd*dd);
    if ((c & 31) == 0) red[c>>5] = s2;
    __syncthreads();

    // fpx
    out[(long long)r*Cn + c] = v;
    // group quant (group 32 == warp)
    float gm = warp_max(fabsf(v));
    float sq = fmaxf(gm / QMAXF, 1e-8f);
    float q  = rintf(v / sq);
    q = fminf(fmaxf(q, -QMAXF), QMAXF);
    long long oq = (long long)BTn*Cn + (long long)r*Cn + c;
    if (oq < osz) out[oq] = q;
    if ((c & 31) == 0){
        long long os = 2LL*BTn*Cn + (long long)r*32 + (c>>5);
        if (os < osz) out[os] = sq;
    }
    if (c == 0){
        float t = 0.f;
#pragma unroll
        for (int i=0;i<32;i++) t += red[i];
        float var = t * (1.0f/Cn);
        float rst = 1.0f / sqrtf(var + 1e-5f);
        long long om = 2LL*BTn*Cn + 32LL*BTn + r;
        if (om < osz)        out[om]       = mu;
        if (om + BTn < osz)  out[om + BTn] = rst;
    }
}

// ---------------- launch ----------------
extern "C" void kernel_launch(void* const* d_in, const int* in_sizes, int n_in,
                              void* d_out, int out_size){
    const float* x     = (const float*)d_in[0];
    const int*   qx    = (const int*)  d_in[1];
    const float* sx    = (const float*)d_in[2];
    const float* meanp = (const float*)d_in[3];
    const float* rstdp = (const float*)d_in[4];
    const float* lnw   = (const float*)d_in[5];
    const float* w1    = (const float*)d_in[6];
    const float* w2    = (const float*)d_in[7];
    float* out = (float*)d_out;

    ln_quant_kernel<<<BTn, Cn>>>(qx, sx, meanp, rstdp, lnw);
    rowquant_kernel<<<3*Cn, Cn>>>(w1, 0, 0);                       // w1 -> g_w1q
    rowquant_kernel<<<Cn,   Cn>>>(w2, 0, 1);                       // w2 -> g_w2q
    gemm_kernel<<<dim3((3*Cn)/128, BTn/64), 256>>>(0);             // qkv
    attn_kernel<<<dim3(Tn/64, Hn, Bn), 256>>>();                   // y
    rowquant_kernel<<<BTn, Cn>>>(nullptr, 1, 2);                   // y fake-quant in place
    gemm_kernel<<<dim3(Cn/128, BTn/64), 256>>>(1);                 // proj
    final_kernel<<<BTn, Cn>>>(x, out, (long long)out_size);
}

// round 2
// speedup vs baseline: 1.3563x; 1.3563x over previous
#include <cuda_runtime.h>
#include <math.h>

#define Bn   2
#define Tn   2048
#define Cn   1024
#define Hn   16
#define HDn  64
#define BTn  (Bn*Tn)          // 4096
#define QMAXF 127.0f

// ---------------- scratch (module globals; no allocation) ----------------
__device__ int   g_qa [BTn*256];        // packed int8 LN output   (4 MB)
__device__ float g_sa [32*BTn];         // scales [group][row]
__device__ int   g_qw1[3*Cn*256];       // packed w1               (3 MB)
__device__ float g_sw1[32*3*Cn];
__device__ int   g_qw2[Cn*256];         // packed w2               (1 MB)
__device__ float g_sw2[32*Cn];
__device__ float g_qkv[BTn*3*Cn];       // qkv fp32               (48 MB)
__device__ int   g_qy [BTn*256];        // packed attention-out    (4 MB)
__device__ float g_sy [32*BTn];
__device__ float g_proj[BTn*Cn];        // proj fp32              (16 MB)

__device__ __forceinline__ float warp_max(float v){
#pragma unroll
    for (int o=16;o;o>>=1) v = fmaxf(v, __shfl_xor_sync(0xffffffffu, v, o));
    return v;
}
__device__ __forceinline__ float warp_sum(float v){
#pragma unroll
    for (int o=16;o;o>>=1) v += __shfl_xor_sync(0xffffffffu, v, o);
    return v;
}
__device__ __forceinline__ float max8(float v){      // max over groups of 8 lanes
#pragma unroll
    for (int o=4;o;o>>=1) v = fmaxf(v, __shfl_xor_sync(0xffffffffu, v, o));
    return v;
}
__device__ __forceinline__ int pack4(float a, float b, float c, float d){
    int i0 = (int)a, i1 = (int)b, i2 = (int)c, i3 = (int)d;
    return (i0 & 0xFF) | ((i1 & 0xFF) << 8) | ((i2 & 0xFF) << 16) | (i3 << 24);
}
__device__ __forceinline__ float qclamp(float h, float inv_s){
    float q = rintf(h * inv_s);
    return fminf(fmaxf(q, -QMAXF), QMAXF);
}

// ---------------- kernel 1: int8 LN + group-32 quantize -> packed int8 ----------------
__global__ void ln_quant_pack(const int* __restrict__ qx, const float* __restrict__ sx,
                              const float* __restrict__ meanp, const float* __restrict__ rstdp,
                              const float* __restrict__ lnw){
    int r = blockIdx.x, t = threadIdx.x;           // 256 threads, 4 channels each
    int c0 = t << 2;
    int4 qv = *(const int4*)(qx + r*Cn + c0);
    float sxv = sx[r*32 + (c0 >> 5)];
    float mu = meanp[r], rs = rstdp[r];
    float4 wv = *(const float4*)(lnw + c0);
    float h0 = ((float)qv.x * sxv - mu) * rs * wv.x;
    float h1 = ((float)qv.y * sxv - mu) * rs * wv.y;
    float h2 = ((float)qv.z * sxv - mu) * rs * wv.z;
    float h3 = ((float)qv.w * sxv - mu) * rs * wv.w;
    float m = fmaxf(fmaxf(fabsf(h0), fabsf(h1)), fmaxf(fabsf(h2), fabsf(h3)));
    m = max8(m);
    float s = fmaxf(m * (1.0f/QMAXF), 1e-8f);
    float inv = 1.0f / s;
    g_qa[r*256 + t] = pack4(qclamp(h0,inv), qclamp(h1,inv), qclamp(h2,inv), qclamp(h3,inv));
    if ((t & 7) == 0) g_sa[(t>>3)*BTn + r] = s;
}

// ---------------- kernel 2: weight group-32 quantize -> packed int8 ----------------
__global__ void wquant_pack(const float* __restrict__ w, int which){
    int* qo = (which == 0) ? g_qw1 : g_qw2;
    float* so = (which == 0) ? g_sw1 : g_sw2;
    int nrows = (which == 0) ? 3*Cn : Cn;
    int r = blockIdx.x, t = threadIdx.x;
    int c0 = t << 2;
    float4 wv = *(const float4*)(w + r*Cn + c0);
    float m = fmaxf(fmaxf(fabsf(wv.x), fabsf(wv.y)), fmaxf(fabsf(wv.z), fabsf(wv.w)));
    m = max8(m);
    float s = fmaxf(m * (1.0f/QMAXF), 1e-8f);
    float inv = 1.0f / s;
    qo[r*256 + t] = pack4(qclamp(wv.x,inv), qclamp(wv.y,inv), qclamp(wv.z,inv), qclamp(wv.w,inv));
    if ((t & 7) == 0) so[(t>>3)*nrows + r] = s;
}

// ---------------- kernel 3: dp4a GEMM  C[M,N] = dequant(A) * dequant(B)^T ----------------
// Tile 128x128, K-chunk = 32 (one quant group, exact int32 dot), 256 threads, 8x8 microtile.
__global__ __launch_bounds__(256) void gemm_dp4a(int which){
    const int* Aq; const float* sA; const int* Bq; const float* sB; float* Cm; int N;
    if (which == 0){ Aq = g_qa; sA = g_sa; Bq = g_qw1; sB = g_sw1; Cm = g_qkv;  N = 3*Cn; }
    else           { Aq = g_qy; sA = g_sy; Bq = g_qw2; sB = g_sw2; Cm = g_proj; N = Cn;   }

    __shared__ __align__(16) int As[8][132];   // [j][m]
    __shared__ __align__(16) int Bs[8][132];   // [j][n]
    __shared__ float sAs[128], sBs[128];

    int tid = threadIdx.x;
    int tx = tid & 15, ty = tid >> 4;
    int bm = blockIdx.y << 7, bn = blockIdx.x << 7;
    int lr = tid >> 1, j0 = (tid & 1) << 2;    // loader: row, j-offset

    float accf[8][8];
#pragma unroll
    for (int i=0;i<8;i++)
#pragma unroll
        for (int j=0;j<8;j++) accf[i][j] = 0.f;

    for (int g = 0; g < 32; g++){
        int4 av = *(const int4*)(Aq + (bm+lr)*256 + (g<<3) + j0);
        int4 bv = *(const int4*)(Bq + (bn+lr)*256 + (g<<3) + j0);
        float sv = (tid < 128) ? sA[g*BTn + bm + tid] : sB[g*N + bn + tid - 128];
        __syncthreads();
        As[j0+0][lr] = av.x; As[j0+1][lr] = av.y; As[j0+2][lr] = av.z; As[j0+3][lr] = av.w;
        Bs[j0+0][lr] = bv.x; Bs[j0+1][lr] = bv.y; Bs[j0+2][lr] = bv.z; Bs[j0+3][lr] = bv.w;
        if (tid < 128) sAs[tid] = sv; else sBs[tid-128] = sv;
        __syncthreads();

        int acc[8][8];
#pragma unroll
        for (int i=0;i<8;i++)
#pragma unroll
            for (int j=0;j<8;j++) acc[i][j] = 0;
#pragma unroll
        for (int j = 0; j < 8; j++){
            int4 a0 = *(const int4*)&As[j][ty<<2];
            int4 a1 = *(const int4*)&As[j][64 + (ty<<2)];
            int4 b0 = *(const int4*)&Bs[j][tx<<2];
            int4 b1 = *(const int4*)&Bs[j][64 + (tx<<2)];
            int aa[8] = {a0.x,a0.y,a0.z,a0.w,a1.x,a1.y,a1.z,a1.w};
            int bb[8] = {b0.x,b0.y,b0.z,b0.w,b1.x,b1.y,b1.z,b1.w};
#pragma unroll
            for (int i=0;i<8;i++)
#pragma unroll
                for (int jj=0;jj<8;jj++) acc[i][jj] = __dp4a(aa[i], bb[jj], acc[i][jj]);
        }
        float sa_[8], sb_[8];
#pragma unroll
        for (int i=0;i<4;i++){ sa_[i] = sAs[(ty<<2)+i]; sa_[i+4] = sAs[64+(ty<<2)+i]; }
#pragma unroll
        for (int j=0;j<4;j++){ sb_[j] = sBs[(tx<<2)+j]; sb_[j+4] = sBs[64+(tx<<2)+j]; }
#pragma unroll
        for (int i=0;i<8;i++)
#pragma unroll
            for (int j=0;j<8;j++)
                accf[i][j] = fmaf(__int2float_rn(acc[i][j]), sa_[i]*sb_[j], accf[i][j]);
    }
#pragma unroll
    for (int i=0;i<8;i++){
        int mrow = bm + ((i<4) ? ((ty<<2)+i) : (64 + (ty<<2) + i - 4));
        float4 c0 = make_float4(accf[i][0],accf[i][1],accf[i][2],accf[i][3]);
        float4 c1 = make_float4(accf[i][4],accf[i][5],accf[i][6],accf[i][7]);
        *(float4*)(Cm + mrow*N + bn +      (tx<<2)) = c0;
        *(float4*)(Cm + mrow*N + bn + 64 + (tx<<2)) = c1;
    }
}

// ---------------- kernel 4: causal flash attention + fused y fake-quant ----------------
__global__ __launch_bounds__(256) void attn_kernel(){
    __shared__ __align__(16) float Qs[64*64];
    __shared__ __align__(16) float Ks[32*68];
    __shared__ __align__(16) float Vs[32*64];

    int qt = blockIdx.x, h = blockIdx.y, b = blockIdx.z;
    int tid = threadIdx.x, w = tid >> 5, l = tid & 31;
    int qs = qt << 6;
    const float* base = g_qkv + (b*Tn)*3*Cn + h*HDn;

#pragma unroll
    for (int it=0; it<4; it++){
        int idx = tid + it*256;
        int r = idx >> 4, d4 = (idx & 15) << 2;
        float4 v = *(const float4*)(base + (qs+r)*3*Cn + d4);
        v.x *= 0.125f; v.y *= 0.125f; v.z *= 0.125f; v.w *= 0.125f;
        *(float4*)&Qs[r*64 + d4] = v;
    }

    float m[8], lsum[8], ax[8], ay[8];
#pragma unroll
    for (int r=0;r<8;r++){ m[r] = -INFINITY; lsum[r]=0.f; ax[r]=0.f; ay[r]=0.f; }

    int ntiles = (qs + 64) >> 5;
    for (int kt=0; kt<ntiles; kt++){
        int ks = kt << 5;
        __syncthreads();
#pragma unroll
        for (int it=0; it<2; it++){
            int idx = tid + it*256;
            int kr = idx >> 4, d4 = (idx & 15) << 2;
            const float* rowp = base + (ks+kr)*3*Cn;
            float4 kv = *(const float4*)(rowp +   Cn + d4);
            float4 vv = *(const float4*)(rowp + 2*Cn + d4);
            *(float4*)&Ks[kr*68 + d4] = kv;
            *(float4*)&Vs[kr*64 + d4] = vv;
        }
        __syncthreads();

        int kg = ks + l;
        const float4* K4 = (const float4*)(Ks + l*68);
        const float2* V2 = (const float2*)Vs;
#pragma unroll
        for (int r=0;r<8;r++){
            int rg = (w<<3) + r;
            const float4* Q4 = (const float4*)(Qs + rg*64);
            float s = 0.f;
#pragma unroll
            for (int d4=0; d4<16; d4++){
                float4 a = Q4[d4], bq = K4[d4];
                s += a.x*bq.x; s += a.y*bq.y; s += a.z*bq.z; s += a.w*bq.w;
            }
            if (kg > qs + rg) s = -1e30f;
            float mn = fmaxf(m[r], warp_max(s));
            float alpha = __expf(m[r] - mn);
            float p = __expf(s - mn);
            lsum[r] = lsum[r]*alpha + warp_sum(p);
            m[r] = mn;
            float a0 = ax[r]*alpha, a1 = ay[r]*alpha;
#pragma unroll
            for (int kk=0; kk<32; kk++){
                float pk = __shfl_sync(0xffffffffu, p, kk);
                float2 vv = V2[(kk<<5) + l];
                a0 += pk*vv.x; a1 += pk*vv.y;
            }
            ax[r] = a0; ay[r] = a1;
        }
    }
    // epilogue: normalize + group-32 fake-quant of y -> packed int8 (+ scales)
#pragma unroll
    for (int r=0;r<8;r++){
        int rg = (w<<3) + r;
        int row = b*Tn + qs + rg;
        float inv = 1.0f / lsum[r];
        float o0 = ax[r]*inv, o1 = ay[r]*inv;
        // channels h*64 + 2l, 2l+1; group of 32 = half-warp
        float gm = fmaxf(fabsf(o0), fabsf(o1));
#pragma unroll
        for (int o=8;o;o>>=1) gm = fmaxf(gm, __shfl_xor_sync(0xffffffffu, gm, o));
        float sq = fmaxf(gm * (1.0f/QMAXF), 1e-8f);
        float isq = 1.0f / sq;
        int q0 = (int)qclamp(o0, isq), q1 = (int)qclamp(o1, isq);
        int sh = (q0 & 0xFF) | ((q1 & 0xFF) << 8);
        int other = __shfl_down_sync(0xffffffffu, sh, 1);
        if (!(l & 1)) g_qy[row*256 + h*16 + (l>>1)] = (sh & 0xFFFF) | (other << 16);
        if (l == 0)  g_sy[(h*2  )*BTn + row] = sq;
        if (l == 16) g_sy[(h*2+1)*BTn + row] = sq;
    }
}

// ---------------- kernel 5: residual + stats + output quant + pack ----------------
__global__ void final_kernel(const float* __restrict__ x, float* __restrict__ out, long long osz){
    __shared__ float red[33];
    int r = blockIdx.x, c = threadIdx.x;
    float v = x[r*Cn + c] + g_proj[r*Cn + c];

    float s1 = warp_sum(v);
    if ((c & 31) == 0) red[c>>5] = s1;
    __syncthreads();
    if (c < 32){
        float t = warp_sum(red[c]);
        if (c == 0) red[32] = t * (1.0f/Cn);
    }
    __syncthreads();
    float mu = red[32];
    float dd = v - mu;
    float s2 = warp_sum(dd*dd);
    if ((c & 31) == 0) red[c>>5] = s2;
    __syncthreads();

    out[(long long)r*Cn + c] = v;
    float gm = warp_max(fabsf(v));
    float sq = fmaxf(gm / QMAXF, 1e-8f);
    float q  = rintf(v / sq);
    q = fminf(fmaxf(q, -QMAXF), QMAXF);
    long long oq = (long long)BTn*Cn + (long long)r*Cn + c;
    if (oq < osz) out[oq] = q;
    if ((c & 31) == 0){
        long long os = 2LL*BTn*Cn + (long long)r*32 + (c>>5);
        if (os < osz) out[os] = sq;
    }
    if (c == 0){
        float t = 0.f;
#pragma unroll
        for (int i=0;i<32;i++) t += red[i];
        float var = t * (1.0f/Cn);
        float rst = 1.0f / sqrtf(var + 1e-5f);
        long long om = 2LL*BTn*Cn + 32LL*BTn + r;
        if (om < osz)        out[om]       = mu;
        if (om + BTn < osz)  out[om + BTn] = rst;
    }
}

// ---------------- launch ----------------
extern "C" void kernel_launch(void* const* d_in, const int* in_sizes, int n_in,
                              void* d_out, int out_size){
    const float* x     = (const float*)d_in[0];
    const int*   qx    = (const int*)  d_in[1];
    const float* sx    = (const float*)d_in[2];
    const float* meanp = (const float*)d_in[3];
    const float* rstdp = (const float*)d_in[4];
    const float* lnw   = (const float*)d_in[5];
    const float* w1    = (const float*)d_in[6];
    const float* w2    = (const float*)d_in[7];
    float* out = (float*)d_out;

    ln_quant_pack<<<BTn, 256>>>(qx, sx, meanp, rstdp, lnw);
    wquant_pack<<<3*Cn, 256>>>(w1, 0);
    wquant_pack<<<Cn,   256>>>(w2, 1);
    gemm_dp4a<<<dim3((3*Cn)/128, BTn/128), 256>>>(0);          // qkv
    attn_kernel<<<dim3(Tn/64, Hn, Bn), 256>>>();               // y (+ fused quant)
    gemm_dp4a<<<dim3(Cn/128, BTn/128), 256>>>(1);              // proj
    final_kernel<<<BTn, Cn>>>(x, out, (long long)out_size);
}

// round 5
// speedup vs baseline: 2.6603x; 1.9615x over previous
#include <cuda_runtime.h>
#include <cuda_bf16.h>
#include <math.h>

#define Bn   2
#define Tn   2048
#define Cn   1024
#define Hn   16
#define HDn  64
#define BTn  (Bn*Tn)
#define QMAXF 127.0f
#define C3   3072
#define QW   36        // padded words per row in attn smem

// ---------------- scratch ----------------
__device__ int   g_qa [BTn*256];
__device__ float g_sa [32*BTn];
__device__ int   g_qw1[3*Cn*256];
__device__ float g_sw1[32*3*Cn];
__device__ int   g_qw2[Cn*256];
__device__ float g_sw2[32*Cn];
__device__ float g_qkv[(size_t)BTn*C3];
__device__ int   g_qy [BTn*256];
__device__ float g_sy [32*BTn];
__device__ float g_proj[(size_t)BTn*Cn];

__device__ __forceinline__ float warp_max(float v){
#pragma unroll
    for (int o=16;o;o>>=1) v = fmaxf(v, __shfl_xor_sync(0xffffffffu, v, o));
    return v;
}
__device__ __forceinline__ float warp_sum(float v){
#pragma unroll
    for (int o=16;o;o>>=1) v += __shfl_xor_sync(0xffffffffu, v, o);
    return v;
}
__device__ __forceinline__ float max8(float v){
#pragma unroll
    for (int o=4;o;o>>=1) v = fmaxf(v, __shfl_xor_sync(0xffffffffu, v, o));
    return v;
}
__device__ __forceinline__ int pack4(float a, float b, float c, float d){
    int i0=(int)a, i1=(int)b, i2=(int)c, i3=(int)d;
    return (i0&0xFF) | ((i1&0xFF)<<8) | ((i2&0xFF)<<16) | (i3<<24);
}
__device__ __forceinline__ float qclamp(float h, float inv_s){
    float q = rintf(h * inv_s);
    return fminf(fmaxf(q, -QMAXF), QMAXF);
}
__device__ __forceinline__ float ex2f(float x){
    float y; asm("ex2.approx.f32 %0, %1;" : "=f"(y) : "f"(x)); return y;
}
__device__ __forceinline__ unsigned pbf2(float x, float y){
    __nv_bfloat162 h = __floats2bfloat162_rn(x, y);
    return *(unsigned*)&h;
}
__device__ __forceinline__ void split2(float x, float y, unsigned &hi, unsigned &lo){
    unsigned h = pbf2(x, y);
    __nv_bfloat162 hb = *(__nv_bfloat162*)&h;
    hi = h;
    lo = pbf2(x - __bfloat162float(hb.x), y - __bfloat162float(hb.y));
}
__device__ __forceinline__ void mma16816(float* d, const unsigned* a, unsigned b0, unsigned b1){
    asm volatile("mma.sync.aligned.m16n8k16.row.col.f32.bf16.bf16.f32 "
        "{%0,%1,%2,%3},{%4,%5,%6,%7},{%8,%9},{%0,%1,%2,%3};"
        : "+f"(d[0]),"+f"(d[1]),"+f"(d[2]),"+f"(d[3])
        : "r"(a[0]),"r"(a[1]),"r"(a[2]),"r"(a[3]), "r"(b0),"r"(b1));
}

// ---------------- kernel 1: LN + quant pack ----------------
__global__ void ln_quant_pack(const int* __restrict__ qx, const float* __restrict__ sx,
                              const float* __restrict__ meanp, const float* __restrict__ rstdp,
                              const float* __restrict__ lnw){
    int r = blockIdx.x, t = threadIdx.x;
    int c0 = t << 2;
    int4 qv = *(const int4*)(qx + r*Cn + c0);
    float sxv = sx[r*32 + (c0 >> 5)];
    float mu = meanp[r], rs = rstdp[r];
    float4 wv = *(const float4*)(lnw + c0);
    float h0 = ((float)qv.x * sxv - mu) * rs * wv.x;
    float h1 = ((float)qv.y * sxv - mu) * rs * wv.y;
    float h2 = ((float)qv.z * sxv - mu) * rs * wv.z;
    float h3 = ((float)qv.w * sxv - mu) * rs * wv.w;
    float m = max8(fmaxf(fmaxf(fabsf(h0),fabsf(h1)), fmaxf(fabsf(h2),fabsf(h3))));
    float s = fmaxf(m * (1.0f/QMAXF), 1e-8f);
    float inv = 1.0f / s;
    g_qa[r*256 + t] = pack4(qclamp(h0,inv), qclamp(h1,inv), qclamp(h2,inv), qclamp(h3,inv));
    if ((t & 7) == 0) g_sa[(t>>3)*BTn + r] = s;
}

// ---------------- kernel 2: weight quant pack ----------------
__global__ void wquant_pack(const float* __restrict__ w, int which){
    int* qo = (which == 0) ? g_qw1 : g_qw2;
    float* so = (which == 0) ? g_sw1 : g_sw2;
    int nrows = (which == 0) ? C3 : Cn;
    int r = blockIdx.x, t = threadIdx.x;
    int c0 = t << 2;
    float4 wv = *(const float4*)(w + r*Cn + c0);
    float m = max8(fmaxf(fmaxf(fabsf(wv.x),fabsf(wv.y)), fmaxf(fabsf(wv.z),fabsf(wv.w))));
    float s = fmaxf(m * (1.0f/QMAXF), 1e-8f);
    float inv = 1.0f / s;
    qo[r*256 + t] = pack4(qclamp(wv.x,inv), qclamp(wv.y,inv), qclamp(wv.z,inv), qclamp(wv.w,inv));
    if ((t & 7) == 0) so[(t>>3)*nrows + r] = s;
}

// ---------------- kernel 3: dp4a GEMM 128x128, 512 thr, double-buffered ----------------
__global__ __launch_bounds__(512) void gemm_dp4a(int which){
    const int* Aq; const float* sA; const int* Bq; const float* sB; float* Cm; int N;
    if (which == 0){ Aq=g_qa; sA=g_sa; Bq=g_qw1; sB=g_sw1; Cm=g_qkv;  N=C3; }
    else           { Aq=g_qy; sA=g_sy; Bq=g_qw2; sB=g_sw2; Cm=g_proj; N=Cn; }

    __shared__ __align__(16) int As[2][8][132];
    __shared__ __align__(16) int Bs[2][8][132];
    __shared__ float sAs[2][128], sBs[2][128];

    int tid = threadIdx.x;
    int tx = tid & 15, ty = tid >> 4;
    int bm = blockIdx.y << 7, bn = blockIdx.x << 7;

    int lrow = (tid < 256) ? (tid >> 1) : ((tid - 256) >> 1);
    int lj = (tid & 1) << 2;
    int4 r; float sreg = 0.f;

    if (tid < 256) r = *(const int4*)(Aq + (bm + lrow)*256 + lj);
    else           r = *(const int4*)(Bq + (bn + lrow)*256 + lj);
    if (tid < 128) sreg = sA[bm + tid];
    else if (tid >= 256 && tid < 384) sreg = sB[bn + tid - 256];
    if (tid < 256){ As[0][lj][lrow]=r.x; As[0][lj+1][lrow]=r.y; As[0][lj+2][lrow]=r.z; As[0][lj+3][lrow]=r.w; }
    else          { Bs[0][lj][lrow]=r.x; Bs[0][lj+1][lrow]=r.y; Bs[0][lj+2][lrow]=r.z; Bs[0][lj+3][lrow]=r.w; }
    if (tid < 128) sAs[0][tid] = sreg;
    else if (tid >= 256 && tid < 384) sBs[0][tid-256] = sreg;
    __syncthreads();

    float accf[4][8];
#pragma unroll
    for (int i=0;i<4;i++)
#pragma unroll
        for (int j=0;j<8;j++) accf[i][j] = 0.f;

    for (int g = 0; g < 32; g++){
        int s = g & 1;
        if (g + 1 < 32){
            if (tid < 256) r = *(const int4*)(Aq + (bm + lrow)*256 + (g+1)*8 + lj);
            else           r = *(const int4*)(Bq + (bn + lrow)*256 + (g+1)*8 + lj);
            if (tid < 128) sreg = sA[(g+1)*BTn + bm + tid];
            else if (tid >= 256 && tid < 384) sreg = sB[(g+1)*N + bn + tid - 256];
        }
        int acc[4][8];
#pragma unroll
        for (int i=0;i<4;i++)
#pragma unroll
            for (int j=0;j<8;j++) acc[i][j] = 0;
#pragma unroll
        for (int j = 0; j < 8; j++){
            int4 a  = *(const int4*)&As[s][j][ty<<2];
            int4 b0 = *(const int4*)&Bs[s][j][tx<<2];
            int4 b1 = *(const int4*)&Bs[s][j][64 + (tx<<2)];
            int aa[4] = {a.x,a.y,a.z,a.w};
            int bb[8] = {b0.x,b0.y,b0.z,b0.w,b1.x,b1.y,b1.z,b1.w};
#pragma unroll
            for (int i=0;i<4;i++)
#pragma unroll
                for (int jj=0;jj<8;jj++) acc[i][jj] = __dp4a(aa[i], bb[jj], acc[i][jj]);
        }
        float sa_[4], sb_[8];
#pragma unroll
        for (int i=0;i<4;i++) sa_[i] = sAs[s][(ty<<2)+i];
#pragma unroll
        for (int j=0;j<4;j++){ sb_[j] = sBs[s][(tx<<2)+j]; sb_[j+4] = sBs[s][64+(tx<<2)+j]; }
#pragma unroll
        for (int i=0;i<4;i++)
#pragma unroll
            for (int j=0;j<8;j++)
                accf[i][j] = fmaf(__int2float_rn(acc[i][j]), sa_[i]*sb_[j], accf[i][j]);
        if (g + 1 < 32){
            int ns = s ^ 1;
            if (tid < 256){ As[ns][lj][lrow]=r.x; As[ns][lj+1][lrow]=r.y; As[ns][lj+2][lrow]=r.z; As[ns][lj+3][lrow]=r.w; }
            else          { Bs[ns][lj][lrow]=r.x; Bs[ns][lj+1][lrow]=r.y; Bs[ns][lj+2][lrow]=r.z; Bs[ns][lj+3][lrow]=r.w; }
            if (tid < 128) sAs[ns][tid] = sreg;
            else if (tid >= 256 && tid < 384) sBs[ns][tid-256] = sreg;
            __syncthreads();
        }
    }
#pragma unroll
    for (int i=0;i<4;i++){
        int mrow = bm + (ty<<2) + i;
        *(float4*)(Cm + (size_t)mrow*N + bn +      (tx<<2)) = make_float4(accf[i][0],accf[i][1],accf[i][2],accf[i][3]);
        *(float4*)(Cm + (size_t)mrow*N + bn + 64 + (tx<<2)) = make_float4(accf[i][4],accf[i][5],accf[i][6],accf[i][7]);
    }
}

// ---------------- kernel 4: flash attention, bf16 mma + hi/lo compensation ----------------
// block = 128 q rows (8 warps x m16), 64-key tiles, d=64. Fused y fake-quant.
__global__ __launch_bounds__(256) void attn_kernel(){
    __shared__ unsigned KH[64*QW], KL[64*QW], VH[64*QW], VL[64*QW];   // 36 KB

    int qt = blockIdx.x, hh = blockIdx.y, b = blockIdx.z;
    int tid = threadIdx.x, w = tid >> 5, lane = tid & 31;
    int g = lane >> 2, tig = lane & 3;
    int qs = qt << 7, qb = w << 4;
    const float* base = g_qkv + (size_t)(b*Tn)*C3 + hh*HDn;
    const float SCALE = 0.125f * 1.44269504088896f;
    int r0 = qs + qb + g, r1 = r0 + 8;

    // Q fragments in registers (hi/lo)
    unsigned aqh[4][4], aql[4][4];
#pragma unroll
    for (int dk=0; dk<4; dk++){
        const float* p0 = base + (size_t)r0*C3 + 16*dk + 2*tig;
        const float* p1 = base + (size_t)r1*C3 + 16*dk + 2*tig;
        float2 v00 = *(const float2*)(p0);
        float2 v01 = *(const float2*)(p0 + 8);
        float2 v10 = *(const float2*)(p1);
        float2 v11 = *(const float2*)(p1 + 8);
        split2(v00.x*SCALE, v00.y*SCALE, aqh[dk][0], aql[dk][0]);
        split2(v10.x*SCALE, v10.y*SCALE, aqh[dk][1], aql[dk][1]);
        split2(v01.x*SCALE, v01.y*SCALE, aqh[dk][2], aql[dk][2]);
        split2(v11.x*SCALE, v11.y*SCALE, aqh[dk][3], aql[dk][3]);
    }

    float o[8][4];
#pragma unroll
    for (int n=0;n<8;n++){ o[n][0]=0.f; o[n][1]=0.f; o[n][2]=0.f; o[n][3]=0.f; }
    float m0 = -INFINITY, m1 = -INFINITY, l0s = 0.f, l1s = 0.f;

    int ntiles = (qs + 128) >> 6;
    for (int kt = 0; kt < ntiles; kt++){
        int ks = kt << 6;
        __syncthreads();
#pragma unroll
        for (int it = 0; it < 4; it++){              // K tile: 64 x 64
            int idx = tid + it*256;
            int row = idx >> 4, d4 = (idx & 15) << 2;
            float4 v = *(const float4*)(base + (size_t)(ks+row)*C3 + Cn + d4);
            unsigned h0,l0,h1,l1;
            split2(v.x, v.y, h0, l0);
            split2(v.z, v.w, h1, l1);
            int wd = row*QW + (d4>>1);
            KH[wd] = h0; KH[wd+1] = h1;
            KL[wd] = l0; KL[wd+1] = l1;
        }
#pragma unroll
        for (int it = 0; it < 8; it++){              // V tile transposed: [d][key-pairs]
            int idx = tid + it*256;
            int d = idx & 63, kw = idx >> 6;
            float v0 = base[(size_t)(ks + 2*kw    )*C3 + 2*Cn + d];
            float v1 = base[(size_t)(ks + 2*kw + 1)*C3 + 2*Cn + d];
            unsigned h, l;
            split2(v0, v1, h, l);
            VH[d*QW + kw] = h;
            VL[d*QW + kw] = l;
        }
        __syncthreads();

        // ---- S = Q K^T (3-term) ----
        float s[8][4];
#pragma unroll
        for (int n=0;n<8;n++){ s[n][0]=0.f; s[n][1]=0.f; s[n][2]=0.f; s[n][3]=0.f; }
#pragma unroll
        for (int dk = 0; dk < 4; dk++){
#pragma unroll
            for (int n = 0; n < 8; n++){
                int kb = (8*n+g)*QW + 8*dk + tig;
                unsigned bh0 = KH[kb], bh1 = KH[kb+4];
                unsigned bl0 = KL[kb], bl1 = KL[kb+4];
                mma16816(s[n], aqh[dk], bh0, bh1);
                mma16816(s[n], aql[dk], bh0, bh1);
                mma16816(s[n], aqh[dk], bl0, bl1);
            }
        }
        // ---- mask + online softmax (base 2) ----
        float mx0 = -INFINITY, mx1 = -INFINITY;
#pragma unroll
        for (int n = 0; n < 8; n++){
            int c0 = ks + 8*n + 2*tig, c1 = c0 + 1;
            if (c0 > r0) s[n][0] = -1e30f;
            if (c1 > r0) s[n][1] = -1e30f;
            if (c0 > r1) s[n][2] = -1e30f;
            if (c1 > r1) s[n][3] = -1e30f;
            mx0 = fmaxf(mx0, fmaxf(s[n][0], s[n][1]));
            mx1 = fmaxf(mx1, fmaxf(s[n][2], s[n][3]));
        }
        mx0 = fmaxf(mx0, __shfl_xor_sync(0xffffffffu, mx0, 1));
        mx0 = fmaxf(mx0, __shfl_xor_sync(0xffffffffu, mx0, 2));
        mx1 = fmaxf(mx1, __shfl_xor_sync(0xffffffffu, mx1, 1));
        mx1 = fmaxf(mx1, __shfl_xor_sync(0xffffffffu, mx1, 2));
        float mn0 = fmaxf(m0, mx0), mn1 = fmaxf(m1, mx1);
        float al0 = ex2f(m0 - mn0), al1 = ex2f(m1 - mn1);
        m0 = mn0; m1 = mn1;
        float rs0 = 0.f, rs1 = 0.f;
#pragma unroll
        for (int n = 0; n < 8; n++){
            s[n][0] = ex2f(s[n][0] - m0);
            s[n][1] = ex2f(s[n][1] - m0);
            s[n][2] = ex2f(s[n][2] - m1);
            s[n][3] = ex2f(s[n][3] - m1);
            rs0 += s[n][0] + s[n][1];
            rs1 += s[n][2] + s[n][3];
        }
        rs0 += __shfl_xor_sync(0xffffffffu, rs0, 1);
        rs0 += __shfl_xor_sync(0xffffffffu, rs0, 2);
        rs1 += __shfl_xor_sync(0xffffffffu, rs1, 1);
        rs1 += __shfl_xor_sync(0xffffffffu, rs1, 2);
        l0s = l0s*al0 + rs0;
        l1s = l1s*al1 + rs1;
#pragma unroll
        for (int n = 0; n < 8; n++){
            o[n][0] *= al0; o[n][1] *= al0;
            o[n][2] *= al1; o[n][3] *= al1;
        }
        // ---- O += P V (3-term), P from S fragments ----
#pragma unroll
        for (int kc = 0; kc < 4; kc++){
            unsigned ph[4], pl[4];
            split2(s[2*kc  ][0], s[2*kc  ][1], ph[0], pl[0]);
            split2(s[2*kc  ][2], s[2*kc  ][3], ph[1], pl[1]);
            split2(s[2*kc+1][0], s[2*kc+1][1], ph[2], pl[2]);
            split2(s[2*kc+1][2], s[2*kc+1][3], ph[3], pl[3]);
#pragma unroll
            for (int nd = 0; nd < 8; nd++){
                int kb = (8*nd+g)*QW + 8*kc + tig;
                unsigned bh0 = VH[kb], bh1 = VH[kb+4];
                unsigned bl0 = VL[kb], bl1 = VL[kb+4];
                mma16816(o[nd], ph, bh0, bh1);
                mma16816(o[nd], pl, bh0, bh1);
                mma16816(o[nd], ph, bl0, bl1);
            }
        }
    }

    // ---- epilogue: normalize + group-32 fake-quant -> g_qy / g_sy ----
    float inv0 = 1.0f / l0s, inv1 = 1.0f / l1s;
    float gm00=0.f, gm01=0.f, gm10=0.f, gm11=0.f;   // [row][group]
#pragma unroll
    for (int nd = 0; nd < 8; nd++){
        float a0 = fabsf(o[nd][0]*inv0), a1 = fabsf(o[nd][1]*inv0);
        float b0 = fabsf(o[nd][2]*inv1), b1 = fabsf(o[nd][3]*inv1);
        if (nd < 4){ gm00 = fmaxf(gm00, fmaxf(a0,a1)); gm10 = fmaxf(gm10, fmaxf(b0,b1)); }
        else       { gm01 = fmaxf(gm01, fmaxf(a0,a1)); gm11 = fmaxf(gm11, fmaxf(b0,b1)); }
    }
#pragma unroll
    for (int off = 1; off <= 2; off <<= 1){
        gm00 = fmaxf(gm00, __shfl_xor_sync(0xffffffffu, gm00, off));
        gm01 = fmaxf(gm01, __shfl_xor_sync(0xffffffffu, gm01, off));
        gm10 = fmaxf(gm10, __shfl_xor_sync(0xffffffffu, gm10, off));
        gm11 = fmaxf(gm11, __shfl_xor_sync(0xffffffffu, gm11, off));
    }
    float sq00 = fmaxf(gm00*(1.0f/QMAXF), 1e-8f), sq01 = fmaxf(gm01*(1.0f/QMAXF), 1e-8f);
    float sq10 = fmaxf(gm10*(1.0f/QMAXF), 1e-8f), sq11 = fmaxf(gm11*(1.0f/QMAXF), 1e-8f);
    int row0 = b*Tn + r0, row1 = b*Tn + r1;
#pragma unroll
    for (int nd = 0; nd < 8; nd++){
        float is0 = (nd<4) ? 1.0f/sq00 : 1.0f/sq01;
        float is1 = (nd<4) ? 1.0f/sq10 : 1.0f/sq11;
        int q0 = (int)qclamp(o[nd][0]*inv0, is0), q1 = (int)qclamp(o[nd][1]*inv0, is0);
        int q2 = (int)qclamp(o[nd][2]*inv1, is1), q3 = (int)qclamp(o[nd][3]*inv1, is1);
        int sh0 = (q0&0xFF) | ((q1&0xFF)<<8);
        int sh1 = (q2&0xFF) | ((q3&0xFF)<<8);
        int ot0 = __shfl_down_sync(0xffffffffu, sh0, 1);
        int ot1 = __shfl_down_sync(0xffffffffu, sh1, 1);
        if (!(tig & 1)){
            int wi = hh*16 + nd*2 + (tig>>1);
            g_qy[row0*256 + wi] = (sh0&0xFFFF) | (ot0<<16);
            g_qy[row1*256 + wi] = (sh1&0xFFFF) | (ot1<<16);
        }
    }
    if (tig == 0){
        g_sy[(hh*2  )*BTn + row0] = sq00;
        g_sy[(hh*2  )*BTn + row1] = sq10;
    }
    if (tig == 1){
        g_sy[(hh*2+1)*BTn + row0] = sq01;
        g_sy[(hh*2+1)*BTn + row1] = sq11;
    }
}

// ---------------- kernel 5: residual + stats + output quant ----------------
__global__ void final_kernel(const float* __restrict__ x, float* __restrict__ out, long long osz){
    __shared__ float red[33];
    int r = blockIdx.x, c = threadIdx.x;
    float v = x[r*Cn + c] + g_proj[(size_t)r*Cn + c];

    float s1 = warp_sum(v);
    if ((c & 31) == 0) red[c>>5] = s1;
    __syncthreads();
    if (c < 32){
        float t = warp_sum(red[c]);
        if (c == 0) red[32] = t * (1.0f/Cn);
    }
    __syncthreads();
    float mu = red[32];
    float dd = v - mu;
    float s2 = warp_sum(dd*dd);
    if ((c & 31) == 0) red[c>>5] = s2;
    __syncthreads();

    out[(long long)r*Cn + c] = v;
    float gm = warp_max(fabsf(v));
    float sq = fmaxf(gm / QMAXF, 1e-8f);
    float q  = qclamp(v, 1.0f/sq);
    long long oq = (long long)BTn*Cn + (long long)r*Cn + c;
    if (oq < osz) out[oq] = q;
    if ((c & 31) == 0){
        long long os = 2LL*BTn*Cn + (long long)r*32 + (c>>5);
        if (os < osz) out[os] = sq;
    }
    if (c == 0){
        float t = 0.f;
#pragma unroll
        for (int i=0;i<32;i++) t += red[i];
        float var = t * (1.0f/Cn);
        float rst = 1.0f / sqrtf(var + 1e-5f);
        long long om = 2LL*BTn*Cn + 32LL*BTn + r;
        if (om < osz)        out[om]       = mu;
        if (om + BTn < osz)  out[om + BTn] = rst;
    }
}

// ---------------- launch ----------------
extern "C" void kernel_launch(void* const* d_in, const int* in_sizes, int n_in,
                              void* d_out, int out_size){
    const float* x     = (const float*)d_in[0];
    const int*   qx    = (const int*)  d_in[1];
    const float* sx    = (const float*)d_in[2];
    const float* meanp = (const float*)d_in[3];
    const float* rstdp = (const float*)d_in[4];
    const float* lnw   = (const float*)d_in[5];
    const float* w1    = (const float*)d_in[6];
    const float* w2    = (const float*)d_in[7];
    float* out = (float*)d_out;

    ln_quant_pack<<<BTn, 256>>>(qx, sx, meanp, rstdp, lnw);
    wquant_pack<<<C3, 256>>>(w1, 0);
    wquant_pack<<<Cn, 256>>>(w2, 1);
    gemm_dp4a<<<dim3(C3/128, BTn/128), 512>>>(0);
    attn_kernel<<<dim3(Tn/128, Hn, Bn), 256>>>();
    gemm_dp4a<<<dim3(Cn/128, BTn/128), 512>>>(1);
    final_kernel<<<BTn, Cn>>>(x, out, (long long)out_size);
}

// round 6
// speedup vs baseline: 4.0094x; 1.5072x over previous
#include <cuda_runtime.h>
#include <cuda_bf16.h>
#include <math.h>

#define Bn   2
#define Tn   2048
#define Cn   1024
#define Hn   16
#define HDn  64
#define BTn  (Bn*Tn)
#define QMAXF 127.0f
#define C3   3072
#define QW   36        // padded words per row in attn smem

// ---------------- scratch ----------------
__device__ int   g_qa [BTn*256];
__device__ float g_sa [32*BTn];
__device__ int   g_qw1[3*Cn*256];
__device__ float g_sw1[32*3*Cn];
__device__ int   g_qw2[Cn*256];
__device__ float g_sw2[32*Cn];
__device__ float g_qkv[(size_t)BTn*C3];
__device__ int   g_qy [BTn*256];
__device__ float g_sy [32*BTn];
__device__ float g_proj[(size_t)BTn*Cn];

__device__ __forceinline__ float warp_max(float v){
#pragma unroll
    for (int o=16;o;o>>=1) v = fmaxf(v, __shfl_xor_sync(0xffffffffu, v, o));
    return v;
}
__device__ __forceinline__ float warp_sum(float v){
#pragma unroll
    for (int o=16;o;o>>=1) v += __shfl_xor_sync(0xffffffffu, v, o);
    return v;
}
__device__ __forceinline__ float max8(float v){
#pragma unroll
    for (int o=4;o;o>>=1) v = fmaxf(v, __shfl_xor_sync(0xffffffffu, v, o));
    return v;
}
__device__ __forceinline__ int pack4(float a, float b, float c, float d){
    int i0=(int)a, i1=(int)b, i2=(int)c, i3=(int)d;
    return (i0&0xFF) | ((i1&0xFF)<<8) | ((i2&0xFF)<<16) | (i3<<24);
}
__device__ __forceinline__ float qclamp(float h, float inv_s){
    float q = rintf(h * inv_s);
    return fminf(fmaxf(q, -QMAXF), QMAXF);
}
__device__ __forceinline__ float ex2f(float x){
    float y; asm("ex2.approx.f32 %0, %1;" : "=f"(y) : "f"(x)); return y;
}
__device__ __forceinline__ unsigned pbf2(float x, float y){
    __nv_bfloat162 h = __floats2bfloat162_rn(x, y);
    return *(unsigned*)&h;
}
__device__ __forceinline__ void split2(float x, float y, unsigned &hi, unsigned &lo){
    unsigned h = pbf2(x, y);
    __nv_bfloat162 hb = *(__nv_bfloat162*)&h;
    hi = h;
    lo = pbf2(x - __bfloat162float(hb.x), y - __bfloat162float(hb.y));
}
__device__ __forceinline__ void mma16816(float* d, const unsigned* a, unsigned b0, unsigned b1){
    asm volatile("mma.sync.aligned.m16n8k16.row.col.f32.bf16.bf16.f32 "
        "{%0,%1,%2,%3},{%4,%5,%6,%7},{%8,%9},{%0,%1,%2,%3};"
        : "+f"(d[0]),"+f"(d[1]),"+f"(d[2]),"+f"(d[3])
        : "r"(a[0]),"r"(a[1]),"r"(a[2]),"r"(a[3]), "r"(b0),"r"(b1));
}
__device__ __forceinline__ void imma16832(int* d, const unsigned* a, unsigned b0, unsigned b1){
    asm volatile("mma.sync.aligned.m16n8k32.row.col.s32.s8.s8.s32 "
        "{%0,%1,%2,%3},{%4,%5,%6,%7},{%8,%9},{%10,%11,%12,%13};"
        : "=r"(d[0]),"=r"(d[1]),"=r"(d[2]),"=r"(d[3])
        : "r"(a[0]),"r"(a[1]),"r"(a[2]),"r"(a[3]), "r"(b0),"r"(b1),
          "r"(0),"r"(0),"r"(0),"r"(0));
}
__device__ __forceinline__ void ldm_x4(unsigned* r, const void* p){
    unsigned ad = (unsigned)__cvta_generic_to_shared(p);
    asm volatile("ldmatrix.sync.aligned.m8n8.x4.shared.b16 {%0,%1,%2,%3}, [%4];"
        : "=r"(r[0]),"=r"(r[1]),"=r"(r[2]),"=r"(r[3]) : "r"(ad));
}
__device__ __forceinline__ float i2f_magic(int d){
    return __int_as_float(d + 0x4B400000) - 12582912.0f;
}

// ---------------- kernel 1: LN + quant pack ----------------
__global__ void ln_quant_pack(const int* __restrict__ qx, const float* __restrict__ sx,
                              const float* __restrict__ meanp, const float* __restrict__ rstdp,
                              const float* __restrict__ lnw){
    int r = blockIdx.x, t = threadIdx.x;
    int c0 = t << 2;
    int4 qv = *(const int4*)(qx + r*Cn + c0);
    float sxv = sx[r*32 + (c0 >> 5)];
    float mu = meanp[r], rs = rstdp[r];
    float4 wv = *(const float4*)(lnw + c0);
    float h0 = ((float)qv.x * sxv - mu) * rs * wv.x;
    float h1 = ((float)qv.y * sxv - mu) * rs * wv.y;
    float h2 = ((float)qv.z * sxv - mu) * rs * wv.z;
    float h3 = ((float)qv.w * sxv - mu) * rs * wv.w;
    float m = max8(fmaxf(fmaxf(fabsf(h0),fabsf(h1)), fmaxf(fabsf(h2),fabsf(h3))));
    float s = fmaxf(m * (1.0f/QMAXF), 1e-8f);
    float inv = 1.0f / s;
    g_qa[r*256 + t] = pack4(qclamp(h0,inv), qclamp(h1,inv), qclamp(h2,inv), qclamp(h3,inv));
    if ((t & 7) == 0) g_sa[(t>>3)*BTn + r] = s;
}

// ---------------- kernel 2: weight quant pack ----------------
__global__ void wquant_pack(const float* __restrict__ w, int which){
    int* qo = (which == 0) ? g_qw1 : g_qw2;
    float* so = (which == 0) ? g_sw1 : g_sw2;
    int nrows = (which == 0) ? C3 : Cn;
    int r = blockIdx.x, t = threadIdx.x;
    int c0 = t << 2;
    float4 wv = *(const float4*)(w + r*Cn + c0);
    float m = max8(fmaxf(fmaxf(fabsf(wv.x),fabsf(wv.y)), fmaxf(fabsf(wv.z),fabsf(wv.w))));
    float s = fmaxf(m * (1.0f/QMAXF), 1e-8f);
    float inv = 1.0f / s;
    qo[r*256 + t] = pack4(qclamp(wv.x,inv), qclamp(wv.y,inv), qclamp(wv.z,inv), qclamp(wv.w,inv));
    if ((t & 7) == 0) so[(t>>3)*nrows + r] = s;
}

// ---------------- kernel 3: int8 tensor-core GEMM, 128x128 tile ----------------
// 256 thr = 8 warps (2M x 4N), warp tile 64x32. One m16n8k32 IMMA per quant group
// (exact int32), group scales applied via fp32 magic-bias conversion.
__global__ __launch_bounds__(256,2) void gemm_imma(int which){
    const int* Aq; const float* sA; const int* Bq; const float* sB; float* Cm; int N;
    if (which == 0){ Aq=g_qa; sA=g_sa; Bq=g_qw1; sB=g_sw1; Cm=g_qkv;  N=C3; }
    else           { Aq=g_qy; sA=g_sy; Bq=g_qw2; sB=g_sw2; Cm=g_proj; N=Cn; }

    __shared__ __align__(16) int As[2][128][12];   // 48B stride: 32B data + 16B pad
    __shared__ __align__(16) int Bs[2][128][12];
    __shared__ float sAs[2][128], sBs[2][128];

    int tid = threadIdx.x, lane = tid & 31, wp = tid >> 5;
    int wM = wp >> 2, wN = wp & 3;
    int bm = blockIdx.y << 7, bn = blockIdx.x << 7;

    int lr = tid >> 1, lw = (tid & 1) << 2;
    int4 av, bv; float sv = 0.f;

    av = *(const int4*)(Aq + (bm + lr)*256 + lw);
    bv = *(const int4*)(Bq + (bn + lr)*256 + lw);
    if (tid < 128) sv = sA[bm + tid];
    else           sv = sB[bn + tid - 128];
    *(int4*)&As[0][lr][lw] = av;
    *(int4*)&Bs[0][lr][lw] = bv;
    if (tid < 128) sAs[0][tid] = sv; else sBs[0][tid-128] = sv;
    __syncthreads();

    float accf[4][4][4];
#pragma unroll
    for (int i=0;i<4;i++)
#pragma unroll
        for (int j=0;j<4;j++){ accf[i][j][0]=0.f; accf[i][j][1]=0.f; accf[i][j][2]=0.f; accf[i][j][3]=0.f; }

    // ldmatrix lane addressing (constant across groups)
    int a_row = (lane & 15), a_wrd = (lane >> 4) << 2;
    int b_row = ((lane >> 4) << 3) + (lane & 7), b_wrd = ((lane >> 3) & 1) << 2;

    for (int g = 0; g < 32; g++){
        int s = g & 1;
        if (g + 1 < 32){
            av = *(const int4*)(Aq + (bm + lr)*256 + (g+1)*8 + lw);
            bv = *(const int4*)(Bq + (bn + lr)*256 + (g+1)*8 + lw);
            if (tid < 128) sv = sA[(g+1)*BTn + bm + tid];
            else           sv = sB[(g+1)*N + bn + tid - 128];
        }
        unsigned a[4][4], bf[2][4];
#pragma unroll
        for (int mc = 0; mc < 4; mc++)
            ldm_x4(a[mc], &As[s][wM*64 + mc*16 + a_row][a_wrd]);
#pragma unroll
        for (int p = 0; p < 2; p++)
            ldm_x4(bf[p], &Bs[s][wN*32 + p*16 + b_row][b_wrd]);

        float sa[8], sb[8];
#pragma unroll
        for (int mc = 0; mc < 4; mc++){
            sa[2*mc  ] = sAs[s][wM*64 + mc*16 + (lane>>2)];
            sa[2*mc+1] = sAs[s][wM*64 + mc*16 + (lane>>2) + 8];
        }
#pragma unroll
        for (int nc = 0; nc < 4; nc++){
            float2 s2 = *(float2*)&sBs[s][wN*32 + nc*8 + ((lane&3)<<1)];
            sb[2*nc] = s2.x; sb[2*nc+1] = s2.y;
        }
#pragma unroll
        for (int mc = 0; mc < 4; mc++){
#pragma unroll
            for (int nc = 0; nc < 4; nc++){
                int d[4];
                imma16832(d, a[mc], bf[nc>>1][(nc&1)*2], bf[nc>>1][(nc&1)*2+1]);
                float f0 = i2f_magic(d[0]) * sa[2*mc];
                float f1 = i2f_magic(d[1]) * sa[2*mc];
                float f2 = i2f_magic(d[2]) * sa[2*mc+1];
                float f3 = i2f_magic(d[3]) * sa[2*mc+1];
                accf[mc][nc][0] = fmaf(f0, sb[2*nc  ], accf[mc][nc][0]);
                accf[mc][nc][1] = fmaf(f1, sb[2*nc+1], accf[mc][nc][1]);
                accf[mc][nc][2] = fmaf(f2, sb[2*nc  ], accf[mc][nc][2]);
                accf[mc][nc][3] = fmaf(f3, sb[2*nc+1], accf[mc][nc][3]);
            }
        }
        if (g + 1 < 32){
            int ns = s ^ 1;
            *(int4*)&As[ns][lr][lw] = av;
            *(int4*)&Bs[ns][lr][lw] = bv;
            if (tid < 128) sAs[ns][tid] = sv; else sBs[ns][tid-128] = sv;
            __syncthreads();
        }
    }
#pragma unroll
    for (int mc = 0; mc < 4; mc++){
#pragma unroll
        for (int nc = 0; nc < 4; nc++){
            int row0 = bm + wM*64 + mc*16 + (lane>>2);
            int col  = bn + wN*32 + nc*8 + ((lane&3)<<1);
            *(float2*)(Cm + (size_t)row0*N + col)     = make_float2(accf[mc][nc][0], accf[mc][nc][1]);
            *(float2*)(Cm + (size_t)(row0+8)*N + col) = make_float2(accf[mc][nc][2], accf[mc][nc][3]);
        }
    }
}

// ---------------- kernel 4: flash attention, bf16 mma + hi/lo compensation ----------------
__global__ __launch_bounds__(256) void attn_kernel(){
    __shared__ unsigned KH[64*QW], KL[64*QW], VH[64*QW], VL[64*QW];   // 36 KB

    int qt = blockIdx.x, hh = blockIdx.y, b = blockIdx.z;
    int tid = threadIdx.x, w = tid >> 5, lane = tid & 31;
    int g = lane >> 2, tig = lane & 3;
    int qs = qt << 7, qb = w << 4;
    const float* base = g_qkv + (size_t)(b*Tn)*C3 + hh*HDn;
    const float SCALE = 0.125f * 1.44269504088896f;
    int r0 = qs + qb + g, r1 = r0 + 8;

    unsigned aqh[4][4], aql[4][4];
#pragma unroll
    for (int dk=0; dk<4; dk++){
        const float* p0 = base + (size_t)r0*C3 + 16*dk + 2*tig;
        const float* p1 = base + (size_t)r1*C3 + 16*dk + 2*tig;
        float2 v00 = *(const float2*)(p0);
        float2 v01 = *(const float2*)(p0 + 8);
        float2 v10 = *(const float2*)(p1);
        float2 v11 = *(const float2*)(p1 + 8);
        split2(v00.x*SCALE, v00.y*SCALE, aqh[dk][0], aql[dk][0]);
        split2(v10.x*SCALE, v10.y*SCALE, aqh[dk][1], aql[dk][1]);
        split2(v01.x*SCALE, v01.y*SCALE, aqh[dk][2], aql[dk][2]);
        split2(v11.x*SCALE, v11.y*SCALE, aqh[dk][3], aql[dk][3]);
    }

    float o[8][4];
#pragma unroll
    for (int n=0;n<8;n++){ o[n][0]=0.f; o[n][1]=0.f; o[n][2]=0.f; o[n][3]=0.f; }
    float m0 = -INFINITY, m1 = -INFINITY, l0s = 0.f, l1s = 0.f;

    int ntiles = (qs + 128) >> 6;
    for (int kt = 0; kt < ntiles; kt++){
        int ks = kt << 6;
        __syncthreads();
#pragma unroll
        for (int it = 0; it < 4; it++){
            int idx = tid + it*256;
            int row = idx >> 4, d4 = (idx & 15) << 2;
            float4 v = *(const float4*)(base + (size_t)(ks+row)*C3 + Cn + d4);
            unsigned h0,l0,h1,l1;
            split2(v.x, v.y, h0, l0);
            split2(v.z, v.w, h1, l1);
            int wd = row*QW + (d4>>1);
            KH[wd] = h0; KH[wd+1] = h1;
            KL[wd] = l0; KL[wd+1] = l1;
        }
#pragma unroll
        for (int it = 0; it < 8; it++){
            int idx = tid + it*256;
            int d = idx & 63, kw = idx >> 6;
            float v0 = base[(size_t)(ks + 2*kw    )*C3 + 2*Cn + d];
            float v1 = base[(size_t)(ks + 2*kw + 1)*C3 + 2*Cn + d];
            unsigned h, l;
            split2(v0, v1, h, l);
            VH[d*QW + kw] = h;
            VL[d*QW + kw] = l;
        }
        __syncthreads();

        float s[8][4];
#pragma unroll
        for (int n=0;n<8;n++){ s[n][0]=0.f; s[n][1]=0.f; s[n][2]=0.f; s[n][3]=0.f; }
#pragma unroll
        for (int dk = 0; dk < 4; dk++){
#pragma unroll
            for (int n = 0; n < 8; n++){
                int kb = (8*n+g)*QW + 8*dk + tig;
                unsigned bh0 = KH[kb], bh1 = KH[kb+4];
                unsigned bl0 = KL[kb], bl1 = KL[kb+4];
                mma16816(s[n], aqh[dk], bh0, bh1);
                mma16816(s[n], aql[dk], bh0, bh1);
                mma16816(s[n], aqh[dk], bl0, bl1);
            }
        }
        float mx0 = -INFINITY, mx1 = -INFINITY;
#pragma unroll
        for (int n = 0; n < 8; n++){
            int c0 = ks + 8*n + 2*tig, c1 = c0 + 1;
            if (c0 > r0) s[n][0] = -1e30f;
            if (c1 > r0) s[n][1] = -1e30f;
            if (c0 > r1) s[n][2] = -1e30f;
            if (c1 > r1) s[n][3] = -1e30f;
            mx0 = fmaxf(mx0, fmaxf(s[n][0], s[n][1]));
            mx1 = fmaxf(mx1, fmaxf(s[n][2], s[n][3]));
        }
        mx0 = fmaxf(mx0, __shfl_xor_sync(0xffffffffu, mx0, 1));
        mx0 = fmaxf(mx0, __shfl_xor_sync(0xffffffffu, mx0, 2));
        mx1 = fmaxf(mx1, __shfl_xor_sync(0xffffffffu, mx1, 1));
        mx1 = fmaxf(mx1, __shfl_xor_sync(0xffffffffu, mx1, 2));
        float mn0 = fmaxf(m0, mx0), mn1 = fmaxf(m1, mx1);
        float al0 = ex2f(m0 - mn0), al1 = ex2f(m1 - mn1);
        m0 = mn0; m1 = mn1;
        float rs0 = 0.f, rs1 = 0.f;
#pragma unroll
        for (int n = 0; n < 8; n++){
            s[n][0] = ex2f(s[n][0] - m0);
            s[n][1] = ex2f(s[n][1] - m0);
            s[n][2] = ex2f(s[n][2] - m1);
            s[n][3] = ex2f(s[n][3] - m1);
            rs0 += s[n][0] + s[n][1];
            rs1 += s[n][2] + s[n][3];
        }
        rs0 += __shfl_xor_sync(0xffffffffu, rs0, 1);
        rs0 += __shfl_xor_sync(0xffffffffu, rs0, 2);
        rs1 += __shfl_xor_sync(0xffffffffu, rs1, 1);
        rs1 += __shfl_xor_sync(0xffffffffu, rs1, 2);
        l0s = l0s*al0 + rs0;
        l1s = l1s*al1 + rs1;
#pragma unroll
        for (int n = 0; n < 8; n++){
            o[n][0] *= al0; o[n][1] *= al0;
            o[n][2] *= al1; o[n][3] *= al1;
        }
#pragma unroll
        for (int kc = 0; kc < 4; kc++){
            unsigned ph[4], pl[4];
            split2(s[2*kc  ][0], s[2*kc  ][1], ph[0], pl[0]);
            split2(s[2*kc  ][2], s[2*kc  ][3], ph[1], pl[1]);
            split2(s[2*kc+1][0], s[2*kc+1][1], ph[2], pl[2]);
            split2(s[2*kc+1][2], s[2*kc+1][3], ph[3], pl[3]);
#pragma unroll
            for (int nd = 0; nd < 8; nd++){
                int kb = (8*nd+g)*QW + 8*kc + tig;
                unsigned bh0 = VH[kb], bh1 = VH[kb+4];
                unsigned bl0 = VL[kb], bl1 = VL[kb+4];
                mma16816(o[nd], ph, bh0, bh1);
                mma16816(o[nd], pl, bh0, bh1);
                mma16816(o[nd], ph, bl0, bl1);
            }
        }
    }

    float inv0 = 1.0f / l0s, inv1 = 1.0f / l1s;
    float gm00=0.f, gm01=0.f, gm10=0.f, gm11=0.f;
#pragma unroll
    for (int nd = 0; nd < 8; nd++){
        float a0 = fabsf(o[nd][0]*inv0), a1 = fabsf(o[nd][1]*inv0);
        float b0 = fabsf(o[nd][2]*inv1), b1 = fabsf(o[nd][3]*inv1);
        if (nd < 4){ gm00 = fmaxf(gm00, fmaxf(a0,a1)); gm10 = fmaxf(gm10, fmaxf(b0,b1)); }
        else       { gm01 = fmaxf(gm01, fmaxf(a0,a1)); gm11 = fmaxf(gm11, fmaxf(b0,b1)); }
    }
#pragma unroll
    for (int off = 1; off <= 2; off <<= 1){
        gm00 = fmaxf(gm00, __shfl_xor_sync(0xffffffffu, gm00, off));
        gm01 = fmaxf(gm01, __shfl_xor_sync(0xffffffffu, gm01, off));
        gm10 = fmaxf(gm10, __shfl_xor_sync(0xffffffffu, gm10, off));
        gm11 = fmaxf(gm11, __shfl_xor_sync(0xffffffffu, gm11, off));
    }
    float sq00 = fmaxf(gm00*(1.0f/QMAXF), 1e-8f), sq01 = fmaxf(gm01*(1.0f/QMAXF), 1e-8f);
    float sq10 = fmaxf(gm10*(1.0f/QMAXF), 1e-8f), sq11 = fmaxf(gm11*(1.0f/QMAXF), 1e-8f);
    int row0 = b*Tn + r0, row1 = b*Tn + r1;
#pragma unroll
    for (int nd = 0; nd < 8; nd++){
        float is0 = (nd<4) ? 1.0f/sq00 : 1.0f/sq01;
        float is1 = (nd<4) ? 1.0f/sq10 : 1.0f/sq11;
        int q0 = (int)qclamp(o[nd][0]*inv0, is0), q1 = (int)qclamp(o[nd][1]*inv0, is0);
        int q2 = (int)qclamp(o[nd][2]*inv1, is1), q3 = (int)qclamp(o[nd][3]*inv1, is1);
        int sh0 = (q0&0xFF) | ((q1&0xFF)<<8);
        int sh1 = (q2&0xFF) | ((q3&0xFF)<<8);
        int ot0 = __shfl_down_sync(0xffffffffu, sh0, 1);
        int ot1 = __shfl_down_sync(0xffffffffu, sh1, 1);
        if (!(tig & 1)){
            int wi = hh*16 + nd*2 + (tig>>1);
            g_qy[row0*256 + wi] = (sh0&0xFFFF) | (ot0<<16);
            g_qy[row1*256 + wi] = (sh1&0xFFFF) | (ot1<<16);
        }
    }
    if (tig == 0){
        g_sy[(hh*2  )*BTn + row0] = sq00;
        g_sy[(hh*2  )*BTn + row1] = sq10;
    }
    if (tig == 1){
        g_sy[(hh*2+1)*BTn + row0] = sq01;
        g_sy[(hh*2+1)*BTn + row1] = sq11;
    }
}

// ---------------- kernel 5: residual + stats + output quant ----------------
__global__ void final_kernel(const float* __restrict__ x, float* __restrict__ out, long long osz){
    __shared__ float red[33];
    int r = blockIdx.x, c = threadIdx.x;
    float v = x[r*Cn + c] + g_proj[(size_t)r*Cn + c];

    float s1 = warp_sum(v);
    if ((c & 31) == 0) red[c>>5] = s1;
    __syncthreads();
    if (c < 32){
        float t = warp_sum(red[c]);
        if (c == 0) red[32] = t * (1.0f/Cn);
    }
    __syncthreads();
    float mu = red[32];
    float dd = v - mu;
    float s2 = warp_sum(dd*dd);
    if ((c & 31) == 0) red[c>>5] = s2;
    __syncthreads();

    out[(long long)r*Cn + c] = v;
    float gm = warp_max(fabsf(v));
    float sq = fmaxf(gm / QMAXF, 1e-8f);
    float q  = qclamp(v, 1.0f/sq);
    long long oq = (long long)BTn*Cn + (long long)r*Cn + c;
    if (oq < osz) out[oq] = q;
    if ((c & 31) == 0){
        long long os = 2LL*BTn*Cn + (long long)r*32 + (c>>5);
        if (os < osz) out[os] = sq;
    }
    if (c == 0){
        float t = 0.f;
#pragma unroll
        for (int i=0;i<32;i++) t += red[i];
        float var = t * (1.0f/Cn);
        float rst = 1.0f / sqrtf(var + 1e-5f);
        long long om = 2LL*BTn*Cn + 32LL*BTn + r;
        if (om < osz)        out[om]       = mu;
        if (om + BTn < osz)  out[om + BTn] = rst;
    }
}

// ---------------- launch ----------------
extern "C" void kernel_launch(void* const* d_in, const int* in_sizes, int n_in,
                              void* d_out, int out_size){
    const float* x     = (const float*)d_in[0];
    const int*   qx    = (const int*)  d_in[1];
    const float* sx    = (const float*)d_in[2];
    const float* meanp = (const float*)d_in[3];
    const float* rstdp = (const float*)d_in[4];
    const float* lnw   = (const float*)d_in[5];
    const float* w1    = (const float*)d_in[6];
    const float* w2    = (const float*)d_in[7];
    float* out = (float*)d_out;

    ln_quant_pack<<<BTn, 256>>>(qx, sx, meanp, rstdp, lnw);
    wquant_pack<<<C3, 256>>>(w1, 0);
    wquant_pack<<<Cn, 256>>>(w2, 1);
    gemm_imma<<<dim3(C3/128, BTn/128), 256>>>(0);
    attn_kernel<<<dim3(Tn/128, Hn, Bn), 256>>>();
    gemm_imma<<<dim3(Cn/128, BTn/128), 256>>>(1);
    final_kernel<<<BTn, Cn>>>(x, out, (long long)out_size);
}

// round 7
// speedup vs baseline: 4.3185x; 1.0771x over previous
#include <cuda_runtime.h>
#include <cuda_bf16.h>
#include <math.h>

#define Bn   2
#define Tn   2048
#define Cn   1024
#define Hn   16
#define HDn  64
#define BTn  (Bn*Tn)
#define QMAXF 127.0f
#define C3   3072
#define QW   36        // padded words per row in attn smem

// ---------------- scratch ----------------
__device__ int   g_qa [BTn*256];
__device__ float g_sa [32*BTn];
__device__ int   g_qw1[3*Cn*256];
__device__ float g_sw1[32*3*Cn];
__device__ int   g_qw2[Cn*256];
__device__ float g_sw2[32*Cn];
__device__ float g_qkv[(size_t)BTn*C3];
__device__ int   g_qy [BTn*256];
__device__ float g_sy [32*BTn];
__device__ float g_proj[(size_t)BTn*Cn];

__device__ __forceinline__ float warp_max(float v){
#pragma unroll
    for (int o=16;o;o>>=1) v = fmaxf(v, __shfl_xor_sync(0xffffffffu, v, o));
    return v;
}
__device__ __forceinline__ float warp_sum(float v){
#pragma unroll
    for (int o=16;o;o>>=1) v += __shfl_xor_sync(0xffffffffu, v, o);
    return v;
}
__device__ __forceinline__ float max8(float v){
#pragma unroll
    for (int o=4;o;o>>=1) v = fmaxf(v, __shfl_xor_sync(0xffffffffu, v, o));
    return v;
}
__device__ __forceinline__ int pack4(float a, float b, float c, float d){
    int i0=(int)a, i1=(int)b, i2=(int)c, i3=(int)d;
    return (i0&0xFF) | ((i1&0xFF)<<8) | ((i2&0xFF)<<16) | (i3<<24);
}
__device__ __forceinline__ float qclamp(float h, float inv_s){
    float q = rintf(h * inv_s);
    return fminf(fmaxf(q, -QMAXF), QMAXF);
}
__device__ __forceinline__ float ex2f(float x){
    float y; asm("ex2.approx.f32 %0, %1;" : "=f"(y) : "f"(x)); return y;
}
__device__ __forceinline__ unsigned pbf2(float x, float y){
    __nv_bfloat162 h = __floats2bfloat162_rn(x, y);
    return *(unsigned*)&h;
}
__device__ __forceinline__ void split2(float x, float y, unsigned &hi, unsigned &lo){
    unsigned h = pbf2(x, y);
    __nv_bfloat162 hb = *(__nv_bfloat162*)&h;
    hi = h;
    lo = pbf2(x - __bfloat162float(hb.x), y - __bfloat162float(hb.y));
}
__device__ __forceinline__ void mma16816(float* d, const unsigned* a, unsigned b0, unsigned b1){
    asm volatile("mma.sync.aligned.m16n8k16.row.col.f32.bf16.bf16.f32 "
        "{%0,%1,%2,%3},{%4,%5,%6,%7},{%8,%9},{%0,%1,%2,%3};"
        : "+f"(d[0]),"+f"(d[1]),"+f"(d[2]),"+f"(d[3])
        : "r"(a[0]),"r"(a[1]),"r"(a[2]),"r"(a[3]), "r"(b0),"r"(b1));
}
__device__ __forceinline__ void imma16832(int* d, const unsigned* a, unsigned b0, unsigned b1){
    asm volatile("mma.sync.aligned.m16n8k32.row.col.s32.s8.s8.s32 "
        "{%0,%1,%2,%3},{%4,%5,%6,%7},{%8,%9},{%10,%11,%12,%13};"
        : "=r"(d[0]),"=r"(d[1]),"=r"(d[2]),"=r"(d[3])
        : "r"(a[0]),"r"(a[1]),"r"(a[2]),"r"(a[3]), "r"(b0),"r"(b1),
          "r"(0),"r"(0),"r"(0),"r"(0));
}
__device__ __forceinline__ void ldm_x4(unsigned* r, const void* p){
    unsigned ad = (unsigned)__cvta_generic_to_shared(p);
    asm volatile("ldmatrix.sync.aligned.m8n8.x4.shared.b16 {%0,%1,%2,%3}, [%4];"
        : "=r"(r[0]),"=r"(r[1]),"=r"(r[2]),"=r"(r[3]) : "r"(ad));
}
// packed f32x2 helpers
__device__ __forceinline__ unsigned long long packf2(float x, float y){
    unsigned long long r; asm("mov.b64 %0, {%1,%2};" : "=l"(r) : "f"(x),"f"(y)); return r;
}
__device__ __forceinline__ unsigned long long pack2i(int x, int y){
    unsigned long long r; asm("mov.b64 %0, {%1,%2};" : "=l"(r) : "r"(x),"r"(y)); return r;
}
__device__ __forceinline__ void unpackf2(unsigned long long v, float &x, float &y){
    asm("mov.b64 {%0,%1}, %2;" : "=f"(x),"=f"(y) : "l"(v));
}
__device__ __forceinline__ unsigned long long addf2(unsigned long long a, unsigned long long b){
    unsigned long long r; asm("add.rn.f32x2 %0, %1, %2;" : "=l"(r) : "l"(a),"l"(b)); return r;
}
__device__ __forceinline__ unsigned long long mulf2(unsigned long long a, unsigned long long b){
    unsigned long long r; asm("mul.rn.f32x2 %0, %1, %2;" : "=l"(r) : "l"(a),"l"(b)); return r;
}
__device__ __forceinline__ unsigned long long fmaf2(unsigned long long a, unsigned long long b, unsigned long long c){
    unsigned long long r; asm("fma.rn.f32x2 %0, %1, %2, %3;" : "=l"(r) : "l"(a),"l"(b),"l"(c)); return r;
}

// ---------------- kernel 1: fused prepass (LN quant + w1 quant + w2 quant) ----------------
__global__ void prepass(const int* __restrict__ qx, const float* __restrict__ sx,
                        const float* __restrict__ meanp, const float* __restrict__ rstdp,
                        const float* __restrict__ lnw,
                        const float* __restrict__ w1, const float* __restrict__ w2){
    int bid = blockIdx.x, t = threadIdx.x;
    int c0 = t << 2;
    if (bid < BTn){
        int r = bid;
        int4 qv = *(const int4*)(qx + r*Cn + c0);
        float sxv = sx[r*32 + (c0 >> 5)];
        float mu = meanp[r], rs = rstdp[r];
        float4 wv = *(const float4*)(lnw + c0);
        float h0 = ((float)qv.x * sxv - mu) * rs * wv.x;
        float h1 = ((float)qv.y * sxv - mu) * rs * wv.y;
        float h2 = ((float)qv.z * sxv - mu) * rs * wv.z;
        float h3 = ((float)qv.w * sxv - mu) * rs * wv.w;
        float m = max8(fmaxf(fmaxf(fabsf(h0),fabsf(h1)), fmaxf(fabsf(h2),fabsf(h3))));
        float s = fmaxf(m * (1.0f/QMAXF), 1e-8f);
        float inv = 1.0f / s;
        g_qa[r*256 + t] = pack4(qclamp(h0,inv), qclamp(h1,inv), qclamp(h2,inv), qclamp(h3,inv));
        if ((t & 7) == 0) g_sa[(t>>3)*BTn + r] = s;
    } else {
        const float* w; int* qo; float* so; int r, nrows;
        if (bid < BTn + C3){ w = w1; qo = g_qw1; so = g_sw1; r = bid - BTn; nrows = C3; }
        else               { w = w2; qo = g_qw2; so = g_sw2; r = bid - BTn - C3; nrows = Cn; }
        float4 wv = *(const float4*)(w + (size_t)r*Cn + c0);
        float m = max8(fmaxf(fmaxf(fabsf(wv.x),fabsf(wv.y)), fmaxf(fabsf(wv.z),fabsf(wv.w))));
        float s = fmaxf(m * (1.0f/QMAXF), 1e-8f);
        float inv = 1.0f / s;
        qo[r*256 + t] = pack4(qclamp(wv.x,inv), qclamp(wv.y,inv), qclamp(wv.z,inv), qclamp(wv.w,inv));
        if ((t & 7) == 0) so[(t>>3)*nrows + r] = s;
    }
}

// ---------------- kernel 3: int8 tensor-core GEMM, packed f32x2 epilogue ----------------
__global__ __launch_bounds__(256,2) void gemm_imma(int which){
    const int* Aq; const float* sA; const int* Bq; const float* sB; float* Cm; int N;
    if (which == 0){ Aq=g_qa; sA=g_sa; Bq=g_qw1; sB=g_sw1; Cm=g_qkv;  N=C3; }
    else           { Aq=g_qy; sA=g_sy; Bq=g_qw2; sB=g_sw2; Cm=g_proj; N=Cn; }

    __shared__ __align__(16) int As[2][128][12];
    __shared__ __align__(16) int Bs[2][128][12];
    __shared__ float sAs[2][128];
    __shared__ __align__(8) float sBs[2][128];

    int tid = threadIdx.x, lane = tid & 31, wp = tid >> 5;
    int wM = wp >> 2, wN = wp & 3;
    int bm = blockIdx.y << 7, bn = blockIdx.x << 7;

    int lr = tid >> 1, lw = (tid & 1) << 2;
    int4 av, bv; float sv = 0.f;

    av = *(const int4*)(Aq + (bm + lr)*256 + lw);
    bv = *(const int4*)(Bq + (bn + lr)*256 + lw);
    if (tid < 128) sv = sA[bm + tid];
    else           sv = sB[bn + tid - 128];
    *(int4*)&As[0][lr][lw] = av;
    *(int4*)&Bs[0][lr][lw] = bv;
    if (tid < 128) sAs[0][tid] = sv; else sBs[0][tid-128] = sv;
    __syncthreads();

    unsigned long long accp[4][4][2];
#pragma unroll
    for (int i=0;i<4;i++)
#pragma unroll
        for (int j=0;j<4;j++){ accp[i][j][0] = 0ull; accp[i][j][1] = 0ull; }

    const unsigned long long negM = packf2(-12582912.0f, -12582912.0f);
    int a_row = (lane & 15), a_wrd = (lane >> 4) << 2;
    int b_row = ((lane >> 4) << 3) + (lane & 7), b_wrd = ((lane >> 3) & 1) << 2;

    for (int g = 0; g < 32; g++){
        int s = g & 1;
        if (g + 1 < 32){
            av = *(const int4*)(Aq + (bm + lr)*256 + (g+1)*8 + lw);
            bv = *(const int4*)(Bq + (bn + lr)*256 + (g+1)*8 + lw);
            if (tid < 128) sv = sA[(g+1)*BTn + bm + tid];
            else           sv = sB[(g+1)*N + bn + tid - 128];
        }
        unsigned a[4][4], bf[2][4];
#pragma unroll
        for (int mc = 0; mc < 4; mc++)
            ldm_x4(a[mc], &As[s][wM*64 + mc*16 + a_row][a_wrd]);
#pragma unroll
        for (int p = 0; p < 2; p++)
            ldm_x4(bf[p], &Bs[s][wN*32 + p*16 + b_row][b_wrd]);

        unsigned long long sa2[8], sb2[4];
#pragma unroll
        for (int mc = 0; mc < 4; mc++){
            float s0 = sAs[s][wM*64 + mc*16 + (lane>>2)];
            float s1 = sAs[s][wM*64 + mc*16 + (lane>>2) + 8];
            sa2[2*mc]   = packf2(s0, s0);
            sa2[2*mc+1] = packf2(s1, s1);
        }
#pragma unroll
        for (int nc = 0; nc < 4; nc++)
            sb2[nc] = *(const unsigned long long*)&sBs[s][wN*32 + nc*8 + ((lane&3)<<1)];

#pragma unroll
        for (int mc = 0; mc < 4; mc++){
#pragma unroll
            for (int nc = 0; nc < 4; nc++){
                int d[4];
                imma16832(d, a[mc], bf[nc>>1][(nc&1)*2], bf[nc>>1][(nc&1)*2+1]);
                unsigned long long p0 = pack2i(d[0] + 0x4B400000, d[1] + 0x4B400000);
                unsigned long long p1 = pack2i(d[2] + 0x4B400000, d[3] + 0x4B400000);
                unsigned long long f0 = addf2(p0, negM);
                unsigned long long f1 = addf2(p1, negM);
                accp[mc][nc][0] = fmaf2(mulf2(f0, sa2[2*mc  ]), sb2[nc], accp[mc][nc][0]);
                accp[mc][nc][1] = fmaf2(mulf2(f1, sa2[2*mc+1]), sb2[nc], accp[mc][nc][1]);
            }
        }
        if (g + 1 < 32){
            int ns = s ^ 1;
            *(int4*)&As[ns][lr][lw] = av;
            *(int4*)&Bs[ns][lr][lw] = bv;
            if (tid < 128) sAs[ns][tid] = sv; else sBs[ns][tid-128] = sv;
            __syncthreads();
        }
    }
#pragma unroll
    for (int mc = 0; mc < 4; mc++){
#pragma unroll
        for (int nc = 0; nc < 4; nc++){
            int row0 = bm + wM*64 + mc*16 + (lane>>2);
            int col  = bn + wN*32 + nc*8 + ((lane&3)<<1);
            float x0,y0,x1,y1;
            unpackf2(accp[mc][nc][0], x0, y0);
            unpackf2(accp[mc][nc][1], x1, y1);
            *(float2*)(Cm + (size_t)row0*N + col)     = make_float2(x0, y0);
            *(float2*)(Cm + (size_t)(row0+8)*N + col) = make_float2(x1, y1);
        }
    }
}

// ---------------- kernel 4: flash attention, bf16 mma + hi/lo compensation ----------------
__global__ __launch_bounds__(256) void attn_kernel(){
    __shared__ unsigned KH[64*QW], KL[64*QW], VH[64*QW], VL[64*QW];   // 36 KB

    int qt = blockIdx.x, hh = blockIdx.y, b = blockIdx.z;
    int tid = threadIdx.x, w = tid >> 5, lane = tid & 31;
    int g = lane >> 2, tig = lane & 3;
    int qs = qt << 7, qb = w << 4;
    const float* base = g_qkv + (size_t)(b*Tn)*C3 + hh*HDn;
    const float SCALE = 0.125f * 1.44269504088896f;
    int r0 = qs + qb + g, r1 = r0 + 8;

    unsigned aqh[4][4], aql[4][4];
#pragma unroll
    for (int dk=0; dk<4; dk++){
        const float* p0 = base + (size_t)r0*C3 + 16*dk + 2*tig;
        const float* p1 = base + (size_t)r1*C3 + 16*dk + 2*tig;
        float2 v00 = *(const float2*)(p0);
        float2 v01 = *(const float2*)(p0 + 8);
        float2 v10 = *(const float2*)(p1);
        float2 v11 = *(const float2*)(p1 + 8);
        split2(v00.x*SCALE, v00.y*SCALE, aqh[dk][0], aql[dk][0]);
        split2(v10.x*SCALE, v10.y*SCALE, aqh[dk][1], aql[dk][1]);
        split2(v01.x*SCALE, v01.y*SCALE, aqh[dk][2], aql[dk][2]);
        split2(v11.x*SCALE, v11.y*SCALE, aqh[dk][3], aql[dk][3]);
    }

    float o[8][4];
#pragma unroll
    for (int n=0;n<8;n++){ o[n][0]=0.f; o[n][1]=0.f; o[n][2]=0.f; o[n][3]=0.f; }
    float m0 = -INFINITY, m1 = -INFINITY, l0s = 0.f, l1s = 0.f;

    int ntiles = (qs + 128) >> 6;
    for (int kt = 0; kt < ntiles; kt++){
        int ks = kt << 6;
        __syncthreads();
#pragma unroll
        for (int it = 0; it < 4; it++){
            int idx = tid + it*256;
            int row = idx >> 4, d4 = (idx & 15) << 2;
            float4 v = *(const float4*)(base + (size_t)(ks+row)*C3 + Cn + d4);
            unsigned h0,l0,h1,l1;
            split2(v.x, v.y, h0, l0);
            split2(v.z, v.w, h1, l1);
            int wd = row*QW + (d4>>1);
            KH[wd] = h0; KH[wd+1] = h1;
            KL[wd] = l0; KL[wd+1] = l1;
        }
#pragma unroll
        for (int it = 0; it < 8; it++){
            int idx = tid + it*256;
            int d = idx & 63, kw = idx >> 6;
            float v0 = base[(size_t)(ks + 2*kw    )*C3 + 2*Cn + d];
            float v1 = base[(size_t)(ks + 2*kw + 1)*C3 + 2*Cn + d];
            unsigned h, l;
            split2(v0, v1, h, l);
            VH[d*QW + kw] = h;
            VL[d*QW + kw] = l;
        }
        __syncthreads();

        float s[8][4];
#pragma unroll
        for (int n=0;n<8;n++){ s[n][0]=0.f; s[n][1]=0.f; s[n][2]=0.f; s[n][3]=0.f; }
#pragma unroll
        for (int dk = 0; dk < 4; dk++){
#pragma unroll
            for (int n = 0; n < 8; n++){
                int kb = (8*n+g)*QW + 8*dk + tig;
                unsigned bh0 = KH[kb], bh1 = KH[kb+4];
                unsigned bl0 = KL[kb], bl1 = KL[kb+4];
                mma16816(s[n], aqh[dk], bh0, bh1);
                mma16816(s[n], aql[dk], bh0, bh1);
                mma16816(s[n], aqh[dk], bl0, bl1);
            }
        }
        float mx0 = -INFINITY, mx1 = -INFINITY;
#pragma unroll
        for (int n = 0; n < 8; n++){
            int c0 = ks + 8*n + 2*tig, c1 = c0 + 1;
            if (c0 > r0) s[n][0] = -1e30f;
            if (c1 > r0) s[n][1] = -1e30f;
            if (c0 > r1) s[n][2] = -1e30f;
            if (c1 > r1) s[n][3] = -1e30f;
            mx0 = fmaxf(mx0, fmaxf(s[n][0], s[n][1]));
            mx1 = fmaxf(mx1, fmaxf(s[n][2], s[n][3]));
        }
        mx0 = fmaxf(mx0, __shfl_xor_sync(0xffffffffu, mx0, 1));
        mx0 = fmaxf(mx0, __shfl_xor_sync(0xffffffffu, mx0, 2));
        mx1 = fmaxf(mx1, __shfl_xor_sync(0xffffffffu, mx1, 1));
        mx1 = fmaxf(mx1, __shfl_xor_sync(0xffffffffu, mx1, 2));
        float mn0 = fmaxf(m0, mx0), mn1 = fmaxf(m1, mx1);
        float al0 = ex2f(m0 - mn0), al1 = ex2f(m1 - mn1);
        m0 = mn0; m1 = mn1;
        float rs0 = 0.f, rs1 = 0.f;
#pragma unroll
        for (int n = 0; n < 8; n++){
            s[n][0] = ex2f(s[n][0] - m0);
            s[n][1] = ex2f(s[n][1] - m0);
            s[n][2] = ex2f(s[n][2] - m1);
            s[n][3] = ex2f(s[n][3] - m1);
            rs0 += s[n][0] + s[n][1];
            rs1 += s[n][2] + s[n][3];
        }
        rs0 += __shfl_xor_sync(0xffffffffu, rs0, 1);
        rs0 += __shfl_xor_sync(0xffffffffu, rs0, 2);
        rs1 += __shfl_xor_sync(0xffffffffu, rs1, 1);
        rs1 += __shfl_xor_sync(0xffffffffu, rs1, 2);
        l0s = l0s*al0 + rs0;
        l1s = l1s*al1 + rs1;
#pragma unroll
        for (int n = 0; n < 8; n++){
            o[n][0] *= al0; o[n][1] *= al0;
            o[n][2] *= al1; o[n][3] *= al1;
        }
#pragma unroll
        for (int kc = 0; kc < 4; kc++){
            unsigned ph[4], pl[4];
            split2(s[2*kc  ][0], s[2*kc  ][1], ph[0], pl[0]);
            split2(s[2*kc  ][2], s[2*kc  ][3], ph[1], pl[1]);
            split2(s[2*kc+1][0], s[2*kc+1][1], ph[2], pl[2]);
            split2(s[2*kc+1][2], s[2*kc+1][3], ph[3], pl[3]);
#pragma unroll
            for (int nd = 0; nd < 8; nd++){
                int kb = (8*nd+g)*QW + 8*kc + tig;
                unsigned bh0 = VH[kb], bh1 = VH[kb+4];
                unsigned bl0 = VL[kb], bl1 = VL[kb+4];
                mma16816(o[nd], ph, bh0, bh1);
                mma16816(o[nd], pl, bh0, bh1);
                mma16816(o[nd], ph, bl0, bl1);
            }
        }
    }

    float inv0 = 1.0f / l0s, inv1 = 1.0f / l1s;
    float gm00=0.f, gm01=0.f, gm10=0.f, gm11=0.f;
#pragma unroll
    for (int nd = 0; nd < 8; nd++){
        float a0 = fabsf(o[nd][0]*inv0), a1 = fabsf(o[nd][1]*inv0);
        float b0 = fabsf(o[nd][2]*inv1), b1 = fabsf(o[nd][3]*inv1);
        if (nd < 4){ gm00 = fmaxf(gm00, fmaxf(a0,a1)); gm10 = fmaxf(gm10, fmaxf(b0,b1)); }
        else       { gm01 = fmaxf(gm01, fmaxf(a0,a1)); gm11 = fmaxf(gm11, fmaxf(b0,b1)); }
    }
#pragma unroll
    for (int off = 1; off <= 2; off <<= 1){
        gm00 = fmaxf(gm00, __shfl_xor_sync(0xffffffffu, gm00, off));
        gm01 = fmaxf(gm01, __shfl_xor_sync(0xffffffffu, gm01, off));
        gm10 = fmaxf(gm10, __shfl_xor_sync(0xffffffffu, gm10, off));
        gm11 = fmaxf(gm11, __shfl_xor_sync(0xffffffffu, gm11, off));
    }
    float sq00 = fmaxf(gm00*(1.0f/QMAXF), 1e-8f), sq01 = fmaxf(gm01*(1.0f/QMAXF), 1e-8f);
    float sq10 = fmaxf(gm10*(1.0f/QMAXF), 1e-8f), sq11 = fmaxf(gm11*(1.0f/QMAXF), 1e-8f);
    int row0 = b*Tn + r0, row1 = b*Tn + r1;
#pragma unroll
    for (int nd = 0; nd < 8; nd++){
        float is0 = (nd<4) ? 1.0f/sq00 : 1.0f/sq01;
        float is1 = (nd<4) ? 1.0f/sq10 : 1.0f/sq11;
        int q0 = (int)qclamp(o[nd][0]*inv0, is0), q1 = (int)qclamp(o[nd][1]*inv0, is0);
        int q2 = (int)qclamp(o[nd][2]*inv1, is1), q3 = (int)qclamp(o[nd][3]*inv1, is1);
        int sh0 = (q0&0xFF) | ((q1&0xFF)<<8);
        int sh1 = (q2&0xFF) | ((q3&0xFF)<<8);
        int ot0 = __shfl_down_sync(0xffffffffu, sh0, 1);
        int ot1 = __shfl_down_sync(0xffffffffu, sh1, 1);
        if (!(tig & 1)){
            int wi = hh*16 + nd*2 + (tig>>1);
            g_qy[row0*256 + wi] = (sh0&0xFFFF) | (ot0<<16);
            g_qy[row1*256 + wi] = (sh1&0xFFFF) | (ot1<<16);
        }
    }
    if (tig == 0){
        g_sy[(hh*2  )*BTn + row0] = sq00;
        g_sy[(hh*2  )*BTn + row1] = sq10;
    }
    if (tig == 1){
        g_sy[(hh*2+1)*BTn + row0] = sq01;
        g_sy[(hh*2+1)*BTn + row1] = sq11;
    }
}

// ---------------- kernel 5: residual + stats + quant, single-pass, 256 thr ----------------
__global__ void final_kernel(const float* __restrict__ x, float* __restrict__ out, long long osz){
    __shared__ float red[8], redq[8], bc[2];
    int r = blockIdx.x, t = threadIdx.x;
    int c0 = t << 2;
    float4 xv = *(const float4*)(x + (size_t)r*Cn + c0);
    float4 pv = *(const float4*)(g_proj + (size_t)r*Cn + c0);
    float v0 = xv.x + pv.x, v1 = xv.y + pv.y, v2 = xv.z + pv.z, v3 = xv.w + pv.w;

    float sum = (v0 + v1) + (v2 + v3);
    float sq  = v0*v0 + v1*v1 + v2*v2 + v3*v3;
    sum = warp_sum(sum);
    sq  = warp_sum(sq);
    if ((t & 31) == 0){ red[t>>5] = sum; redq[t>>5] = sq; }
    __syncthreads();
    if (t < 32){
        float a = (t < 8) ? red[t]  : 0.f;
        float b = (t < 8) ? redq[t] : 0.f;
#pragma unroll
        for (int o=4;o;o>>=1){ a += __shfl_xor_sync(0xffffffffu, a, o); b += __shfl_xor_sync(0xffffffffu, b, o); }
        if (t == 0){
            float mu = a * (1.0f/Cn);
            float var = b * (1.0f/Cn) - mu*mu;
            bc[0] = mu;
            bc[1] = 1.0f / sqrtf(var + 1e-5f);
        }
    }
    __syncthreads();
    float mu = bc[0], rst = bc[1];

    // fpx
    *(float4*)(out + (size_t)r*Cn + c0) = make_float4(v0, v1, v2, v3);
    // group-32 quant
    float m = max8(fmaxf(fmaxf(fabsf(v0),fabsf(v1)), fmaxf(fabsf(v2),fabsf(v3))));
    float s = fmaxf(m * (1.0f/QMAXF), 1e-8f);
    float inv = 1.0f / s;
    long long oq = (long long)BTn*Cn + (long long)r*Cn + c0;
    if (oq + 3 < osz)
        *(float4*)(out + oq) = make_float4(qclamp(v0,inv), qclamp(v1,inv), qclamp(v2,inv), qclamp(v3,inv));
    if ((t & 7) == 0){
        long long os = 2LL*BTn*Cn + (long long)r*32 + (t>>3);
        if (os < osz) out[os] = s;
    }
    if (t == 0){
        long long om = 2LL*BTn*Cn + 32LL*BTn + r;
        if (om < osz)        out[om]       = mu;
        if (om + BTn < osz)  out[om + BTn] = rst;
    }
}

// ---------------- launch ----------------
extern "C" void kernel_launch(void* const* d_in, const int* in_sizes, int n_in,
                              void* d_out, int out_size){
    const float* x     = (const float*)d_in[0];
    const int*   qx    = (const int*)  d_in[1];
    const float* sx    = (const float*)d_in[2];
    const float* meanp = (const float*)d_in[3];
    const float* rstdp = (const float*)d_in[4];
    const float* lnw   = (const float*)d_in[5];
    const float* w1    = (const float*)d_in[6];
    const float* w2    = (const float*)d_in[7];
    float* out = (float*)d_out;

    prepass<<<BTn + C3 + Cn, 256>>>(qx, sx, meanp, rstdp, lnw, w1, w2);
    gemm_imma<<<dim3(C3/128, BTn/128), 256>>>(0);
    attn_kernel<<<dim3(Tn/128, Hn, Bn), 256>>>();
    gemm_imma<<<dim3(Cn/128, BTn/128), 256>>>(1);
    final_kernel<<<BTn, 256>>>(x, out, (long long)out_size);
}